// round 1
// baseline (speedup 1.0000x reference)
#include <cuda_runtime.h>

#define D_MODEL 1024
#define N_HEADS 16
#define HEAD_DIM 64
#define BATCH 4
#define SEQ 2048
#define M_ROWS (BATCH * SEQ)     /* 8192 */
#define QKV_N (3 * D_MODEL)      /* 3072 */

// Scratch (allocation-free): qkv = [8192, 3072] fp32, attn = [8192, 1024] fp32
__device__ float g_qkv[(size_t)M_ROWS * QKV_N];
__device__ float g_attn[(size_t)M_ROWS * D_MODEL];

// ---------------------------------------------------------------------------
// SGEMM: C[M,N] = A[M,K] @ B[K,N] + bias[N]
// 128x128 block tile, BK=8, 256 threads, 8x8 per-thread microtile.
// M,N multiples of 128; K multiple of 8. No bounds checks needed (fixed shapes).
// ---------------------------------------------------------------------------
__global__ __launch_bounds__(256) void sgemm_bias(
    const float* __restrict__ A, const float* __restrict__ B,
    const float* __restrict__ bias, float* __restrict__ C,
    int M, int N, int K)
{
    const int BK = 8;
    __shared__ float As[BK][128];   // transposed: As[k][m]
    __shared__ float Bs[BK][128];   // Bs[k][n]

    const int tid = threadIdx.x;
    const int bm = blockIdx.y * 128;
    const int bn = blockIdx.x * 128;

    // A tile load: 128 rows x 8 cols = 256 float4 (one per thread)
    const int arow = tid >> 1;            // 0..127
    const int acol = (tid & 1) * 4;       // 0 or 4
    // B tile load: 8 rows x 128 cols = 256 float4
    const int brow = tid >> 5;            // 0..7
    const int bcol = (tid & 31) * 4;      // 0..124

    const int ty = tid >> 4;              // 0..15 (row group)
    const int tx = tid & 15;              // 0..15 (col group)

    float acc[8][8];
    #pragma unroll
    for (int i = 0; i < 8; i++)
        #pragma unroll
        for (int j = 0; j < 8; j++) acc[i][j] = 0.0f;

    const float* Aptr = A + (size_t)(bm + arow) * K + acol;
    const float* Bptr = B + (size_t)brow * N + bn + bcol;

    for (int k0 = 0; k0 < K; k0 += BK) {
        float4 av = *(const float4*)(Aptr + k0);
        As[acol + 0][arow] = av.x;
        As[acol + 1][arow] = av.y;
        As[acol + 2][arow] = av.z;
        As[acol + 3][arow] = av.w;
        float4 bv = *(const float4*)(Bptr + (size_t)k0 * N);
        *(float4*)&Bs[brow][bcol] = bv;
        __syncthreads();

        #pragma unroll
        for (int k = 0; k < BK; k++) {
            float af[8], bf[8];
            *(float4*)(af + 0) = *(const float4*)&As[k][ty * 8 + 0];
            *(float4*)(af + 4) = *(const float4*)&As[k][ty * 8 + 4];
            *(float4*)(bf + 0) = *(const float4*)&Bs[k][tx * 8 + 0];
            *(float4*)(bf + 4) = *(const float4*)&Bs[k][tx * 8 + 4];
            #pragma unroll
            for (int i = 0; i < 8; i++)
                #pragma unroll
                for (int j = 0; j < 8; j++)
                    acc[i][j] += af[i] * bf[j];
        }
        __syncthreads();
    }

    // Epilogue: add bias, store float4
    #pragma unroll
    for (int i = 0; i < 8; i++) {
        const size_t row = (size_t)(bm + ty * 8 + i);
        #pragma unroll
        for (int j = 0; j < 8; j += 4) {
            const int col = bn + tx * 8 + j;
            float4 v;
            v.x = acc[i][j + 0] + bias[col + 0];
            v.y = acc[i][j + 1] + bias[col + 1];
            v.z = acc[i][j + 2] + bias[col + 2];
            v.w = acc[i][j + 3] + bias[col + 3];
            *(float4*)&C[row * N + col] = v;
        }
    }
}

// ---------------------------------------------------------------------------
// Flash attention (fp32, causal, online softmax).
// Block: 64 queries x full head-dim 64. K/V processed in 32-key tiles.
// 256 threads: ty = tid/8 (0..31) -> 2 query rows each; tx = tid%8.
// Scores: each thread computes 2 rows x 4 key cols. PV: 2 rows x 8 dims.
// qkv layout: [B*S, 3072] row-major; Q at col h*64, K at 1024+h*64, V at 2048+h*64.
// Output attn: [B, S, H, Dh] = [8192, 1024] row-major.
// ---------------------------------------------------------------------------
__global__ __launch_bounds__(256) void attn_kernel(
    const float* __restrict__ qkv, float* __restrict__ attn)
{
    const int qt = blockIdx.x;              // query tile, 0..31
    const int bh = blockIdx.y;              // 0..63
    const int b = bh / N_HEADS;
    const int h = bh % N_HEADS;

    __shared__ float Qst[64][66];   // [d][q], scaled by 1/sqrt(Dh)
    __shared__ float Kst[64][36];   // [d][k]
    __shared__ float Vs[32][68];    // [k][d]
    __shared__ float Ps[64][36];    // [q][k]

    const int tid = threadIdx.x;
    const int ty = tid >> 3;        // 0..31
    const int tx = tid & 7;         // 0..7
    const int r0 = ty * 2;          // query rows r0, r0+1

    const float scale = 0.125f;     // 1/sqrt(64)

    // Load Q tile [64 q][64 d] -> Qst[d][q] (scaled)
    for (int i = tid; i < 64 * 16; i += 256) {
        const int r = i >> 4;
        const int d4 = (i & 15) * 4;
        const float4 qv = *(const float4*)&qkv[
            (size_t)(b * SEQ + qt * 64 + r) * QKV_N + h * HEAD_DIM + d4];
        Qst[d4 + 0][r] = qv.x * scale;
        Qst[d4 + 1][r] = qv.y * scale;
        Qst[d4 + 2][r] = qv.z * scale;
        Qst[d4 + 3][r] = qv.w * scale;
    }

    float o[2][8];
    #pragma unroll
    for (int i = 0; i < 2; i++)
        #pragma unroll
        for (int j = 0; j < 8; j++) o[i][j] = 0.0f;
    float m_r[2] = {-1e30f, -1e30f};
    float l_r[2] = {0.0f, 0.0f};

    const int kt_max = qt * 2 + 1;  // causal: keys only up to qt*64+63

    for (int kt = 0; kt <= kt_max; kt++) {
        __syncthreads();  // protect Kst/Vs/Ps from previous iter (also covers Q on iter 0)

        // Load K tile -> Kst[d][k], V tile -> Vs[k][d]  (32 keys x 64 dims)
        for (int i = tid; i < 32 * 16; i += 256) {
            const int r = i >> 4;
            const int d4 = (i & 15) * 4;
            const size_t base = (size_t)(b * SEQ + kt * 32 + r) * QKV_N + h * HEAD_DIM + d4;
            const float4 kv = *(const float4*)&qkv[base + D_MODEL];
            Kst[d4 + 0][r] = kv.x;
            Kst[d4 + 1][r] = kv.y;
            Kst[d4 + 2][r] = kv.z;
            Kst[d4 + 3][r] = kv.w;
            const float4 vv = *(const float4*)&qkv[base + 2 * D_MODEL];
            *(float4*)&Vs[r][d4] = vv;
        }
        __syncthreads();

        // S = Q K^T (scaled Q): 2 rows x 4 cols per thread
        float s[2][4];
        #pragma unroll
        for (int i = 0; i < 2; i++)
            #pragma unroll
            for (int j = 0; j < 4; j++) s[i][j] = 0.0f;

        #pragma unroll 8
        for (int d = 0; d < 64; d++) {
            const float q0 = Qst[d][r0];
            const float q1 = Qst[d][r0 + 1];
            const float4 kv = *(const float4*)&Kst[d][tx * 4];
            s[0][0] += q0 * kv.x; s[0][1] += q0 * kv.y;
            s[0][2] += q0 * kv.z; s[0][3] += q0 * kv.w;
            s[1][0] += q1 * kv.x; s[1][1] += q1 * kv.y;
            s[1][2] += q1 * kv.z; s[1][3] += q1 * kv.w;
        }

        // Causal mask (only needed on/near diagonal tiles)
        if (kt >= 2 * qt) {
            #pragma unroll
            for (int i = 0; i < 2; i++) {
                const int qg = qt * 64 + r0 + i;
                #pragma unroll
                for (int j = 0; j < 4; j++) {
                    const int kg = kt * 32 + tx * 4 + j;
                    if (kg > qg) s[i][j] = -1e30f;
                }
            }
        }

        // Row max (reduce over 8 tx lanes; tx = low 3 bits of lane id)
        float mt[2];
        #pragma unroll
        for (int i = 0; i < 2; i++) {
            float mm = fmaxf(fmaxf(s[i][0], s[i][1]), fmaxf(s[i][2], s[i][3]));
            mm = fmaxf(mm, __shfl_xor_sync(0xffffffffu, mm, 1));
            mm = fmaxf(mm, __shfl_xor_sync(0xffffffffu, mm, 2));
            mm = fmaxf(mm, __shfl_xor_sync(0xffffffffu, mm, 4));
            mt[i] = mm;
        }

        float corr[2];
        #pragma unroll
        for (int i = 0; i < 2; i++) {
            const float mnew = fmaxf(m_r[i], mt[i]);
            corr[i] = __expf(m_r[i] - mnew);
            m_r[i] = mnew;
        }

        // p = exp(s - m), row sums
        float ls[2];
        #pragma unroll
        for (int i = 0; i < 2; i++) {
            float sum = 0.0f;
            #pragma unroll
            for (int j = 0; j < 4; j++) {
                s[i][j] = __expf(s[i][j] - m_r[i]);
                sum += s[i][j];
            }
            sum += __shfl_xor_sync(0xffffffffu, sum, 1);
            sum += __shfl_xor_sync(0xffffffffu, sum, 2);
            sum += __shfl_xor_sync(0xffffffffu, sum, 4);
            ls[i] = sum;
        }

        // Rescale accumulators and l
        #pragma unroll
        for (int i = 0; i < 2; i++) {
            l_r[i] = l_r[i] * corr[i] + ls[i];
            #pragma unroll
            for (int j = 0; j < 8; j++) o[i][j] *= corr[i];
        }

        // Store P to smem
        *(float4*)&Ps[r0][tx * 4]     = make_float4(s[0][0], s[0][1], s[0][2], s[0][3]);
        *(float4*)&Ps[r0 + 1][tx * 4] = make_float4(s[1][0], s[1][1], s[1][2], s[1][3]);
        __syncthreads();

        // O += P @ V : 2 rows x 8 dims per thread
        const int c0 = tx * 8;
        #pragma unroll 8
        for (int k = 0; k < 32; k++) {
            const float p0 = Ps[r0][k];
            const float p1 = Ps[r0 + 1][k];
            const float4 v0 = *(const float4*)&Vs[k][c0];
            const float4 v1 = *(const float4*)&Vs[k][c0 + 4];
            o[0][0] += p0 * v0.x; o[0][1] += p0 * v0.y;
            o[0][2] += p0 * v0.z; o[0][3] += p0 * v0.w;
            o[0][4] += p0 * v1.x; o[0][5] += p0 * v1.y;
            o[0][6] += p0 * v1.z; o[0][7] += p0 * v1.w;
            o[1][0] += p1 * v0.x; o[1][1] += p1 * v0.y;
            o[1][2] += p1 * v0.z; o[1][3] += p1 * v0.w;
            o[1][4] += p1 * v1.x; o[1][5] += p1 * v1.y;
            o[1][6] += p1 * v1.z; o[1][7] += p1 * v1.w;
        }
    }

    // Epilogue: normalize and write to attn[B,S,H,Dh]
    #pragma unroll
    for (int i = 0; i < 2; i++) {
        const float inv = 1.0f / l_r[i];
        const int q = qt * 64 + r0 + i;
        float* dst = &attn[(size_t)(b * SEQ + q) * D_MODEL + h * HEAD_DIM + tx * 8];
        float4 w0, w1;
        w0.x = o[i][0] * inv; w0.y = o[i][1] * inv;
        w0.z = o[i][2] * inv; w0.w = o[i][3] * inv;
        w1.x = o[i][4] * inv; w1.y = o[i][5] * inv;
        w1.z = o[i][6] * inv; w1.w = o[i][7] * inv;
        *(float4*)(dst + 0) = w0;
        *(float4*)(dst + 4) = w1;
    }
}

extern "C" void kernel_launch(void* const* d_in, const int* in_sizes, int n_in,
                              void* d_out, int out_size)
{
    const float* x     = (const float*)d_in[0];
    const float* qkv_w = (const float*)d_in[1];
    const float* qkv_b = (const float*)d_in[2];
    const float* out_w = (const float*)d_in[3];
    const float* out_b = (const float*)d_in[4];
    float* out = (float*)d_out;

    float* qkv;
    float* attn;
    cudaGetSymbolAddress((void**)&qkv, g_qkv);
    cudaGetSymbolAddress((void**)&attn, g_attn);

    // 1) QKV projection: [8192,1024] @ [1024,3072] + b
    dim3 g1(QKV_N / 128, M_ROWS / 128);
    sgemm_bias<<<g1, 256>>>(x, qkv_w, qkv_b, qkv, M_ROWS, QKV_N, D_MODEL);

    // 2) Causal flash attention per (b,h)
    dim3 g2(SEQ / 64, BATCH * N_HEADS);
    attn_kernel<<<g2, 256>>>(qkv, attn);

    // 3) Output projection: [8192,1024] @ [1024,1024] + b
    dim3 g3(D_MODEL / 128, M_ROWS / 128);
    sgemm_bias<<<g3, 256>>>(attn, out_w, out_b, out, M_ROWS, D_MODEL, D_MODEL);
}

// round 2
// speedup vs baseline: 3.6088x; 3.6088x over previous
#include <cuda_runtime.h>
#include <cstdint>

#define D_MODEL 1024
#define N_HEADS 16
#define HEAD_DIM 64
#define BATCH 4
#define SEQ 2048
#define M_ROWS (BATCH * SEQ)     /* 8192 */
#define QKV_N (3 * D_MODEL)      /* 3072 */

// Scratch (allocation-free): qkv = [8192, 3072] fp32, attn = [8192, 1024] fp32
__device__ float g_qkv[(size_t)M_ROWS * QKV_N];
__device__ float g_attn[(size_t)M_ROWS * D_MODEL];

// ---------------------------------------------------------------------------
// tf32 helpers
// ---------------------------------------------------------------------------
__device__ __forceinline__ uint32_t f2tf32(float x) {
    uint32_t r;
    asm("cvt.rna.tf32.f32 %0, %1;" : "=r"(r) : "f"(x));
    return r;
}

__device__ __forceinline__ void mma_tf32(float* c, const uint32_t* a,
                                         uint32_t b0, uint32_t b1) {
    asm volatile(
        "mma.sync.aligned.m16n8k8.row.col.f32.tf32.tf32.f32 "
        "{%0,%1,%2,%3}, {%4,%5,%6,%7}, {%8,%9}, {%0,%1,%2,%3};\n"
        : "+f"(c[0]), "+f"(c[1]), "+f"(c[2]), "+f"(c[3])
        : "r"(a[0]), "r"(a[1]), "r"(a[2]), "r"(a[3]), "r"(b0), "r"(b1));
}

// ---------------------------------------------------------------------------
// tf32 tensor-core GEMM: C[M,N] = A[M,K] @ B[K,N] + bias[N]
// 128x128 block tile, BK=16, 256 threads (8 warps), warp tile 64x32.
// As stored [k][m] stride 136, Bs stored [k][n] stride 136:
// fragment loads hit 32 distinct banks (bank = 8*q + g + const).
// ---------------------------------------------------------------------------
__global__ __launch_bounds__(256) void gemm_tf32(
    const float* __restrict__ A, const float* __restrict__ B,
    const float* __restrict__ bias, float* __restrict__ C,
    int M, int N, int K)
{
    __shared__ uint32_t As[16][136];
    __shared__ uint32_t Bs[16][136];

    const int tid  = threadIdx.x;
    const int wid  = tid >> 5;
    const int lane = tid & 31;
    const int g = lane >> 2;          // 0..7
    const int q = lane & 3;           // 0..3
    const int wm = (wid >> 2) * 64;   // 0 / 64
    const int wn = (wid & 3) * 32;    // 0..96
    const int bm = blockIdx.y * 128;
    const int bn = blockIdx.x * 128;

    // staging indices
    const int arow = tid >> 1;        // 0..127
    const int acol = (tid & 1) * 8;   // 0 / 8
    const int brow = tid >> 4;        // 0..15
    const int bcol = (tid & 15) * 8;  // 0..120

    float acc[4][4][4];
    #pragma unroll
    for (int i = 0; i < 4; i++)
        #pragma unroll
        for (int j = 0; j < 4; j++)
            #pragma unroll
            for (int r = 0; r < 4; r++) acc[i][j][r] = 0.0f;

    const float* Ap = A + (size_t)(bm + arow) * K + acol;
    const float* Bp = B + (size_t)brow * N + bn + bcol;

    for (int k0 = 0; k0 < K; k0 += 16) {
        // prefetch gmem (issued before sync -> overlaps previous compute)
        float4 av0 = *(const float4*)(Ap + k0);
        float4 av1 = *(const float4*)(Ap + k0 + 4);
        float4 bv0 = *(const float4*)(Bp + (size_t)k0 * N);
        float4 bv1 = *(const float4*)(Bp + (size_t)k0 * N + 4);

        __syncthreads();   // previous compute done before overwrite

        As[acol + 0][arow] = f2tf32(av0.x);
        As[acol + 1][arow] = f2tf32(av0.y);
        As[acol + 2][arow] = f2tf32(av0.z);
        As[acol + 3][arow] = f2tf32(av0.w);
        As[acol + 4][arow] = f2tf32(av1.x);
        As[acol + 5][arow] = f2tf32(av1.y);
        As[acol + 6][arow] = f2tf32(av1.z);
        As[acol + 7][arow] = f2tf32(av1.w);

        uint4 bw0, bw1;
        bw0.x = f2tf32(bv0.x); bw0.y = f2tf32(bv0.y);
        bw0.z = f2tf32(bv0.z); bw0.w = f2tf32(bv0.w);
        bw1.x = f2tf32(bv1.x); bw1.y = f2tf32(bv1.y);
        bw1.z = f2tf32(bv1.z); bw1.w = f2tf32(bv1.w);
        *(uint4*)&Bs[brow][bcol + 0] = bw0;
        *(uint4*)&Bs[brow][bcol + 4] = bw1;

        __syncthreads();

        #pragma unroll
        for (int ks = 0; ks < 2; ks++) {
            const int kk = ks * 8;
            uint32_t af[4][4];
            #pragma unroll
            for (int mt = 0; mt < 4; mt++) {
                const int m0 = wm + mt * 16;
                af[mt][0] = As[kk + q][m0 + g];
                af[mt][1] = As[kk + q][m0 + g + 8];
                af[mt][2] = As[kk + q + 4][m0 + g];
                af[mt][3] = As[kk + q + 4][m0 + g + 8];
            }
            #pragma unroll
            for (int nt = 0; nt < 4; nt++) {
                const int n0 = wn + nt * 8;
                const uint32_t b0 = Bs[kk + q][n0 + g];
                const uint32_t b1 = Bs[kk + q + 4][n0 + g];
                #pragma unroll
                for (int mt = 0; mt < 4; mt++)
                    mma_tf32(acc[mt][nt], af[mt], b0, b1);
            }
        }
    }

    // Epilogue: bias + store (fragment rows g / g+8, cols 2q, 2q+1)
    #pragma unroll
    for (int nt = 0; nt < 4; nt++) {
        const int col = bn + wn + nt * 8 + 2 * q;
        const float bia0 = bias[col];
        const float bia1 = bias[col + 1];
        #pragma unroll
        for (int mt = 0; mt < 4; mt++) {
            const int row0 = bm + wm + mt * 16 + g;
            float2 v0, v1;
            v0.x = acc[mt][nt][0] + bia0;
            v0.y = acc[mt][nt][1] + bia1;
            v1.x = acc[mt][nt][2] + bia0;
            v1.y = acc[mt][nt][3] + bia1;
            *(float2*)&C[(size_t)row0 * N + col] = v0;
            *(float2*)&C[(size_t)(row0 + 8) * N + col] = v1;
        }
    }
}

// ---------------------------------------------------------------------------
// Flash attention with tf32 tensor cores (causal, online softmax).
// Block = 64 queries x one (b,h). 4 warps x 32 = 128 threads; each warp owns
// 16 query rows. KV tiles of 64. Q fragments live in registers (loaded once).
// K smem buffer is reused for P. Layout strides chosen conflict-free:
//   KPs stride 68 (bank = 4g+q), Vs stride 72 (bank = 8q+g).
// ---------------------------------------------------------------------------
__global__ __launch_bounds__(128) void attn_tf32(
    const float* __restrict__ qkv, float* __restrict__ attn)
{
    const int qt = blockIdx.x;            // 0..31 (64 queries each)
    const int bh = blockIdx.y;            // 0..63
    const int b = bh / N_HEADS;
    const int h = bh % N_HEADS;

    __shared__ uint32_t KPs[64][68];      // K tile (as tf32), later P tile
    __shared__ uint32_t Vs[64][72];       // V tile (as tf32)

    const int tid  = threadIdx.x;
    const int wid  = tid >> 5;            // 0..3
    const int lane = tid & 31;
    const int g = lane >> 2;              // 0..7
    const int q = lane & 3;               // 0..3
    const int qbase = wid * 16;           // warp's query rows [qbase, qbase+16)

    const float scale = 0.125f;           // 1/sqrt(64)

    // Load Q fragments once (8 k-steps over head dim), pre-scaled.
    uint32_t qf[8][4];
    {
        const size_t row0 = (size_t)(b * SEQ + qt * 64 + qbase + g) * QKV_N + h * HEAD_DIM;
        const size_t row1 = row0 + (size_t)8 * QKV_N;
        #pragma unroll
        for (int kd = 0; kd < 8; kd++) {
            const int c0 = kd * 8 + q;
            qf[kd][0] = f2tf32(qkv[row0 + c0] * scale);
            qf[kd][1] = f2tf32(qkv[row1 + c0] * scale);
            qf[kd][2] = f2tf32(qkv[row0 + c0 + 4] * scale);
            qf[kd][3] = f2tf32(qkv[row1 + c0 + 4] * scale);
        }
    }

    float of[8][4];
    #pragma unroll
    for (int nt = 0; nt < 8; nt++)
        #pragma unroll
        for (int r = 0; r < 4; r++) of[nt][r] = 0.0f;
    float m0 = -1e30f, m1 = -1e30f;       // running max (rows g, g+8)
    float l0 = 0.0f, l1 = 0.0f;           // running sum

    for (int kt = 0; kt <= qt; kt++) {
        __syncthreads();  // previous PV reads done before K/V overwrite

        // Stage K and V tiles (64 keys x 64 dims), convert to tf32
        for (int i = tid; i < 64 * 16; i += 128) {
            const int r = i >> 4;
            const int d4 = (i & 15) * 4;
            const size_t base =
                (size_t)(b * SEQ + kt * 64 + r) * QKV_N + h * HEAD_DIM + d4;
            const float4 kv = *(const float4*)&qkv[base + D_MODEL];
            KPs[r][d4 + 0] = f2tf32(kv.x);
            KPs[r][d4 + 1] = f2tf32(kv.y);
            KPs[r][d4 + 2] = f2tf32(kv.z);
            KPs[r][d4 + 3] = f2tf32(kv.w);
            const float4 vv = *(const float4*)&qkv[base + 2 * D_MODEL];
            Vs[r][d4 + 0] = f2tf32(vv.x);
            Vs[r][d4 + 1] = f2tf32(vv.y);
            Vs[r][d4 + 2] = f2tf32(vv.z);
            Vs[r][d4 + 3] = f2tf32(vv.w);
        }
        __syncthreads();

        // S = Q K^T : per warp m16 x n64, k=64
        float sf[8][4];
        #pragma unroll
        for (int nt = 0; nt < 8; nt++)
            #pragma unroll
            for (int r = 0; r < 4; r++) sf[nt][r] = 0.0f;

        #pragma unroll
        for (int kd = 0; kd < 8; kd++) {
            #pragma unroll
            for (int nt = 0; nt < 8; nt++) {
                const uint32_t b0 = KPs[nt * 8 + g][kd * 8 + q];
                const uint32_t b1 = KPs[nt * 8 + g][kd * 8 + q + 4];
                mma_tf32(sf[nt], qf[kd], b0, b1);
            }
        }

        // Causal mask (diagonal tile only)
        if (kt == qt) {
            const int qr0 = qbase + g;
            const int qr1 = qr0 + 8;
            #pragma unroll
            for (int nt = 0; nt < 8; nt++) {
                const int kc = nt * 8 + 2 * q;
                if (kc > qr0)     sf[nt][0] = -1e30f;
                if (kc + 1 > qr0) sf[nt][1] = -1e30f;
                if (kc > qr1)     sf[nt][2] = -1e30f;
                if (kc + 1 > qr1) sf[nt][3] = -1e30f;
            }
        }

        // Row max across registers + quad lanes (xor 1,2 varies q only)
        float mt0 = -1e30f, mt1 = -1e30f;
        #pragma unroll
        for (int nt = 0; nt < 8; nt++) {
            mt0 = fmaxf(mt0, fmaxf(sf[nt][0], sf[nt][1]));
            mt1 = fmaxf(mt1, fmaxf(sf[nt][2], sf[nt][3]));
        }
        mt0 = fmaxf(mt0, __shfl_xor_sync(0xffffffffu, mt0, 1));
        mt0 = fmaxf(mt0, __shfl_xor_sync(0xffffffffu, mt0, 2));
        mt1 = fmaxf(mt1, __shfl_xor_sync(0xffffffffu, mt1, 1));
        mt1 = fmaxf(mt1, __shfl_xor_sync(0xffffffffu, mt1, 2));

        const float mn0 = fmaxf(m0, mt0);
        const float mn1 = fmaxf(m1, mt1);
        const float corr0 = __expf(m0 - mn0);
        const float corr1 = __expf(m1 - mn1);
        m0 = mn0; m1 = mn1;

        // p = exp(s - m), partial row sums
        float ls0 = 0.0f, ls1 = 0.0f;
        #pragma unroll
        for (int nt = 0; nt < 8; nt++) {
            sf[nt][0] = __expf(sf[nt][0] - m0);
            sf[nt][1] = __expf(sf[nt][1] - m0);
            sf[nt][2] = __expf(sf[nt][2] - m1);
            sf[nt][3] = __expf(sf[nt][3] - m1);
            ls0 += sf[nt][0] + sf[nt][1];
            ls1 += sf[nt][2] + sf[nt][3];
        }
        ls0 += __shfl_xor_sync(0xffffffffu, ls0, 1);
        ls0 += __shfl_xor_sync(0xffffffffu, ls0, 2);
        ls1 += __shfl_xor_sync(0xffffffffu, ls1, 1);
        ls1 += __shfl_xor_sync(0xffffffffu, ls1, 2);
        l0 = l0 * corr0 + ls0;
        l1 = l1 * corr1 + ls1;

        // Rescale O accumulators
        #pragma unroll
        for (int nt = 0; nt < 8; nt++) {
            of[nt][0] *= corr0; of[nt][1] *= corr0;
            of[nt][2] *= corr1; of[nt][3] *= corr1;
        }

        // Write P (tf32) into the K buffer
        __syncthreads();  // all warps done reading K
        {
            const int r0 = qbase + g;
            #pragma unroll
            for (int nt = 0; nt < 8; nt++) {
                const int kc = nt * 8 + 2 * q;
                KPs[r0][kc]         = f2tf32(sf[nt][0]);
                KPs[r0][kc + 1]     = f2tf32(sf[nt][1]);
                KPs[r0 + 8][kc]     = f2tf32(sf[nt][2]);
                KPs[r0 + 8][kc + 1] = f2tf32(sf[nt][3]);
            }
        }
        __syncthreads();

        // O += P @ V : per warp m16 x n64(dims), k=64(keys)
        #pragma unroll
        for (int ks = 0; ks < 8; ks++) {
            uint32_t pa[4];
            pa[0] = KPs[qbase + g][ks * 8 + q];
            pa[1] = KPs[qbase + g + 8][ks * 8 + q];
            pa[2] = KPs[qbase + g][ks * 8 + q + 4];
            pa[3] = KPs[qbase + g + 8][ks * 8 + q + 4];
            #pragma unroll
            for (int nt = 0; nt < 8; nt++) {
                const uint32_t b0 = Vs[ks * 8 + q][nt * 8 + g];
                const uint32_t b1 = Vs[ks * 8 + q + 4][nt * 8 + g];
                mma_tf32(of[nt], pa, b0, b1);
            }
        }
    }

    // Epilogue: normalize and write attn[B,S,H,Dh]
    const float inv0 = 1.0f / l0;
    const float inv1 = 1.0f / l1;
    const size_t orow0 = (size_t)(b * SEQ + qt * 64 + qbase + g) * D_MODEL + h * HEAD_DIM;
    const size_t orow1 = orow0 + (size_t)8 * D_MODEL;
    #pragma unroll
    for (int nt = 0; nt < 8; nt++) {
        const int col = nt * 8 + 2 * q;
        float2 v0, v1;
        v0.x = of[nt][0] * inv0; v0.y = of[nt][1] * inv0;
        v1.x = of[nt][2] * inv1; v1.y = of[nt][3] * inv1;
        *(float2*)&attn[orow0 + col] = v0;
        *(float2*)&attn[orow1 + col] = v1;
    }
}

extern "C" void kernel_launch(void* const* d_in, const int* in_sizes, int n_in,
                              void* d_out, int out_size)
{
    const float* x     = (const float*)d_in[0];
    const float* qkv_w = (const float*)d_in[1];
    const float* qkv_b = (const float*)d_in[2];
    const float* out_w = (const float*)d_in[3];
    const float* out_b = (const float*)d_in[4];
    float* out = (float*)d_out;

    float* qkv;
    float* attn;
    cudaGetSymbolAddress((void**)&qkv, g_qkv);
    cudaGetSymbolAddress((void**)&attn, g_attn);

    // 1) QKV projection: [8192,1024] @ [1024,3072] + b
    dim3 g1(QKV_N / 128, M_ROWS / 128);
    gemm_tf32<<<g1, 256>>>(x, qkv_w, qkv_b, qkv, M_ROWS, QKV_N, D_MODEL);

    // 2) Causal flash attention per (b,h)
    dim3 g2(SEQ / 64, BATCH * N_HEADS);
    attn_tf32<<<g2, 128>>>(qkv, attn);

    // 3) Output projection: [8192,1024] @ [1024,1024] + b
    dim3 g3(D_MODEL / 128, M_ROWS / 128);
    gemm_tf32<<<g3, 256>>>(attn, out_w, out_b, out, M_ROWS, D_MODEL, D_MODEL);
}

// round 3
// speedup vs baseline: 7.0703x; 1.9592x over previous
#include <cuda_runtime.h>
#include <cuda_fp16.h>
#include <cstdint>

#define D_MODEL 1024
#define N_HEADS 16
#define HEAD_DIM 64
#define BATCH 4
#define SEQ 2048
#define M_ROWS (BATCH * SEQ)     /* 8192 */
#define QKV_N (3 * D_MODEL)      /* 3072 */

// Scratch (allocation-free)
__device__ __half g_xh[(size_t)M_ROWS * D_MODEL];
__device__ __half g_w1h[(size_t)D_MODEL * QKV_N];
__device__ __half g_w2h[(size_t)D_MODEL * D_MODEL];
__device__ __half g_qkvh[(size_t)M_ROWS * QKV_N];
__device__ __half g_attnh[(size_t)M_ROWS * D_MODEL];

// ---------------------------------------------------------------------------
// helpers
// ---------------------------------------------------------------------------
__device__ __forceinline__ uint32_t pack_h2(float x, float y) {
    __half2 h = __floats2half2_rn(x, y);
    return *reinterpret_cast<uint32_t*>(&h);
}

__device__ __forceinline__ void mma_f16(float* c, const uint32_t* a,
                                        uint32_t b0, uint32_t b1) {
    asm volatile(
        "mma.sync.aligned.m16n8k16.row.col.f32.f16.f16.f32 "
        "{%0,%1,%2,%3}, {%4,%5,%6,%7}, {%8,%9}, {%0,%1,%2,%3};\n"
        : "+f"(c[0]), "+f"(c[1]), "+f"(c[2]), "+f"(c[3])
        : "r"(a[0]), "r"(a[1]), "r"(a[2]), "r"(a[3]), "r"(b0), "r"(b1));
}

// interleave halves of two uint4 (8 halves each) into 8 packed-pair words
__device__ __forceinline__ void interleave8(const uint4& a, const uint4& b,
                                            uint32_t* o) {
    o[0] = (a.x & 0xffffu) | (b.x << 16);
    o[1] = (a.x >> 16)     | (b.x & 0xffff0000u);
    o[2] = (a.y & 0xffffu) | (b.y << 16);
    o[3] = (a.y >> 16)     | (b.y & 0xffff0000u);
    o[4] = (a.z & 0xffffu) | (b.z << 16);
    o[5] = (a.z >> 16)     | (b.z & 0xffff0000u);
    o[6] = (a.w & 0xffffu) | (b.w << 16);
    o[7] = (a.w >> 16)     | (b.w & 0xffff0000u);
}

__global__ void cvt_f32_f16(const float* __restrict__ in,
                            __half* __restrict__ out, int n) {
    int i = (blockIdx.x * blockDim.x + threadIdx.x) * 8;
    if (i >= n) return;
    float4 v0 = *(const float4*)(in + i);
    float4 v1 = *(const float4*)(in + i + 4);
    uint4 o;
    o.x = pack_h2(v0.x, v0.y); o.y = pack_h2(v0.z, v0.w);
    o.z = pack_h2(v1.x, v1.y); o.w = pack_h2(v1.z, v1.w);
    *(uint4*)(out + i) = o;
}

// ---------------------------------------------------------------------------
// fp16 tensor-core GEMM: C = A[M,K] @ B[K,N] + bias. 128x128 tile, BK=32,
// 256 threads (8 warps, warp 64x32), double-buffered smem, reg prefetch.
// As2: [m][k-pair] stride 20 (bank 20g+q conflict-free).
// Bs2: [k-pair][n] stride 136 (bank 8q+g conflict-free).
// ---------------------------------------------------------------------------
template<bool OUT_HALF>
__global__ __launch_bounds__(256, 2) void gemm_f16(
    const __half* __restrict__ A, const __half* __restrict__ B,
    const float* __restrict__ bias, void* __restrict__ Cv,
    int M, int N, int K)
{
    __shared__ __align__(16) uint32_t As2[2][128][20];
    __shared__ __align__(16) uint32_t Bs2[2][16][136];

    const int tid  = threadIdx.x;
    const int wid  = tid >> 5;
    const int lane = tid & 31;
    const int g = lane >> 2;
    const int q = lane & 3;
    const int wm = (wid >> 2) * 64;
    const int wn = (wid & 3) * 32;
    const int bm = blockIdx.y * 128;
    const int bn = blockIdx.x * 128;

    const int arow = tid >> 1;
    const int aoff = (tid & 1) * 16;      // halves
    const int awc  = (tid & 1) * 8;       // words
    const int brp  = tid >> 4;            // 0..15 k-pair
    const int bcol = (tid & 15) * 8;      // n cols / words

    float acc[4][4][4];
    #pragma unroll
    for (int i = 0; i < 4; i++)
        #pragma unroll
        for (int j = 0; j < 4; j++)
            #pragma unroll
            for (int r = 0; r < 4; r++) acc[i][j][r] = 0.0f;

    const __half* Ap = A + (size_t)(bm + arow) * K + aoff;
    const __half* Bp0 = B + (size_t)(2 * brp) * N + bn + bcol;
    const __half* Bp1 = Bp0 + N;

    // prologue: stage k0=0 into buf 0
    {
        uint4 a0v = *(const uint4*)(Ap);
        uint4 a1v = *(const uint4*)(Ap + 8);
        uint4 b0v = *(const uint4*)(Bp0);
        uint4 b1v = *(const uint4*)(Bp1);
        *(uint4*)&As2[0][arow][awc]     = a0v;
        *(uint4*)&As2[0][arow][awc + 4] = a1v;
        uint32_t bw[8];
        interleave8(b0v, b1v, bw);
        *(uint4*)&Bs2[0][brp][bcol]     = *(uint4*)(bw);
        *(uint4*)&Bs2[0][brp][bcol + 4] = *(uint4*)(bw + 4);
    }
    __syncthreads();

    const int kIters = K >> 5;
    int s = 0;
    for (int it = 0; it < kIters; ++it) {
        uint4 a0v, a1v, b0v, b1v;
        const bool pre = (it + 1 < kIters);
        if (pre) {
            const int k0 = (it + 1) * 32;
            a0v = *(const uint4*)(Ap + k0);
            a1v = *(const uint4*)(Ap + k0 + 8);
            b0v = *(const uint4*)(Bp0 + (size_t)k0 * N);
            b1v = *(const uint4*)(Bp1 + (size_t)k0 * N);
        }

        #pragma unroll
        for (int ks = 0; ks < 2; ks++) {
            uint32_t af[4][4];
            #pragma unroll
            for (int mt = 0; mt < 4; mt++) {
                const int m0 = wm + mt * 16;
                af[mt][0] = As2[s][m0 + g][ks * 8 + q];
                af[mt][1] = As2[s][m0 + g + 8][ks * 8 + q];
                af[mt][2] = As2[s][m0 + g][ks * 8 + q + 4];
                af[mt][3] = As2[s][m0 + g + 8][ks * 8 + q + 4];
            }
            #pragma unroll
            for (int nt = 0; nt < 4; nt++) {
                const uint32_t b0 = Bs2[s][ks * 8 + q][wn + nt * 8 + g];
                const uint32_t b1 = Bs2[s][ks * 8 + q + 4][wn + nt * 8 + g];
                #pragma unroll
                for (int mt = 0; mt < 4; mt++)
                    mma_f16(acc[mt][nt], af[mt], b0, b1);
            }
        }

        if (pre) {
            *(uint4*)&As2[s ^ 1][arow][awc]     = a0v;
            *(uint4*)&As2[s ^ 1][arow][awc + 4] = a1v;
            uint32_t bw[8];
            interleave8(b0v, b1v, bw);
            *(uint4*)&Bs2[s ^ 1][brp][bcol]     = *(uint4*)(bw);
            *(uint4*)&Bs2[s ^ 1][brp][bcol + 4] = *(uint4*)(bw + 4);
            __syncthreads();
            s ^= 1;
        }
    }

    // Epilogue
    #pragma unroll
    for (int nt = 0; nt < 4; nt++) {
        const int col = bn + wn + nt * 8 + 2 * q;
        const float bia0 = bias[col];
        const float bia1 = bias[col + 1];
        #pragma unroll
        for (int mt = 0; mt < 4; mt++) {
            const int row0 = bm + wm + mt * 16 + g;
            if (OUT_HALF) {
                __half* C = (__half*)Cv;
                *(uint32_t*)&C[(size_t)row0 * N + col] =
                    pack_h2(acc[mt][nt][0] + bia0, acc[mt][nt][1] + bia1);
                *(uint32_t*)&C[(size_t)(row0 + 8) * N + col] =
                    pack_h2(acc[mt][nt][2] + bia0, acc[mt][nt][3] + bia1);
            } else {
                float* C = (float*)Cv;
                float2 v0, v1;
                v0.x = acc[mt][nt][0] + bia0; v0.y = acc[mt][nt][1] + bia1;
                v1.x = acc[mt][nt][2] + bia0; v1.y = acc[mt][nt][3] + bia1;
                *(float2*)&C[(size_t)row0 * N + col] = v0;
                *(float2*)&C[(size_t)(row0 + 8) * N + col] = v1;
            }
        }
    }
}

// ---------------------------------------------------------------------------
// fp16 flash attention, causal, online softmax, double-buffered K/V,
// P kept in registers (accumulator layout == fp16 A-fragment layout).
// Block = 128 queries x one (b,h); 8 warps x 16 query rows; KV tiles of 64.
// Ks2: [dim-pair][key] stride 72; Vs2: [key-pair][dim] stride 72.
// ---------------------------------------------------------------------------
__global__ __launch_bounds__(256, 2) void attn_f16(
    const __half* __restrict__ qkvh, __half* __restrict__ attnh)
{
    const int qt = blockIdx.x;            // 0..15 (128 queries each)
    const int bh = blockIdx.y;
    const int b = bh >> 4;
    const int h = bh & 15;

    __shared__ __align__(16) uint32_t Ks2[2][32][72];
    __shared__ __align__(16) uint32_t Vs2[2][32][72];

    const int tid  = threadIdx.x;
    const int wid  = tid >> 5;            // 0..7
    const int lane = tid & 31;
    const int g = lane >> 2;
    const int q = lane & 3;

    const int qrow_g  = qt * 128 + wid * 16 + g;    // global query row (in seq)
    const int qrow_g8 = qrow_g + 8;

    // staging indices
    const int kr   = tid >> 2;            // 0..63 key
    const int kdw  = (tid & 3) * 8;       // K: word offset (dim-pairs), covers 8 dps
    const int vrp  = tid >> 3;            // 0..31 key-pair
    const int vc   = (tid & 7) * 8;       // V: dim word offset

    const __half* Kg = qkvh + (size_t)(b * SEQ + kr) * QKV_N + D_MODEL + h * HEAD_DIM + kdw * 2;
    const __half* Vg0 = qkvh + (size_t)(b * SEQ + 2 * vrp) * QKV_N + 2 * D_MODEL + h * HEAD_DIM + vc;
    const __half* Vg1 = Vg0 + QKV_N;
    const size_t kvStep = (size_t)64 * QKV_N;   // advance one 64-key tile

    // Q fragments (persistent)
    uint32_t qf[4][4];
    {
        const __half* qp = qkvh + (size_t)(b * SEQ + qrow_g) * QKV_N + h * HEAD_DIM;
        const __half* qp8 = qp + (size_t)8 * QKV_N;
        #pragma unroll
        for (int j = 0; j < 4; j++) {
            qf[j][0] = *(const uint32_t*)(qp  + 16 * j + 2 * q);
            qf[j][1] = *(const uint32_t*)(qp8 + 16 * j + 2 * q);
            qf[j][2] = *(const uint32_t*)(qp  + 16 * j + 2 * q + 8);
            qf[j][3] = *(const uint32_t*)(qp8 + 16 * j + 2 * q + 8);
        }
    }

    float of[8][4];
    #pragma unroll
    for (int nt = 0; nt < 8; nt++)
        #pragma unroll
        for (int r = 0; r < 4; r++) of[nt][r] = 0.0f;
    float m0 = -1e30f, m1 = -1e30f, l0 = 0.0f, l1 = 0.0f;

    const int ktmax   = 2 * qt + 1;                         // last KV tile
    const int myktmax = (qt * 128 + wid * 16 + 15) >> 6;    // last tile this warp touches

    // prologue: stage tile 0 into buf 0
    {
        uint4 k0v = *(const uint4*)(Kg);
        uint4 k1v = *(const uint4*)(Kg + 8);
        const uint32_t* kw0 = (const uint32_t*)&k0v;
        const uint32_t* kw1 = (const uint32_t*)&k1v;
        #pragma unroll
        for (int i = 0; i < 4; i++) Ks2[0][kdw + i][kr] = kw0[i];
        #pragma unroll
        for (int i = 0; i < 4; i++) Ks2[0][kdw + 4 + i][kr] = kw1[i];
        uint4 va = *(const uint4*)(Vg0);
        uint4 vb = *(const uint4*)(Vg1);
        uint32_t vw[8];
        interleave8(va, vb, vw);
        *(uint4*)&Vs2[0][vrp][vc]     = *(uint4*)(vw);
        *(uint4*)&Vs2[0][vrp][vc + 4] = *(uint4*)(vw + 4);
    }
    __syncthreads();

    int s = 0;
    for (int kt = 0; kt <= ktmax; kt++) {
        const bool active = (kt <= myktmax);
        const bool pre = (kt < ktmax);

        float sf[8][4];
        if (active) {
            #pragma unroll
            for (int nt = 0; nt < 8; nt++)
                #pragma unroll
                for (int r = 0; r < 4; r++) sf[nt][r] = 0.0f;
            // S = Q K^T
            #pragma unroll
            for (int j = 0; j < 4; j++) {
                #pragma unroll
                for (int nt = 0; nt < 8; nt++) {
                    const uint32_t b0 = Ks2[s][8 * j + q][nt * 8 + g];
                    const uint32_t b1 = Ks2[s][8 * j + q + 4][nt * 8 + g];
                    mma_f16(sf[nt], qf[j], b0, b1);
                }
            }
        }

        // prefetch next K/V tile into registers (overlaps softmax)
        uint4 k0v, k1v, va, vb;
        if (pre) {
            const size_t off = (size_t)(kt + 1) * kvStep;
            k0v = *(const uint4*)(Kg + off);
            k1v = *(const uint4*)(Kg + off + 8);
            va  = *(const uint4*)(Vg0 + off);
            vb  = *(const uint4*)(Vg1 + off);
        }

        if (active) {
            // scale + causal mask
            #pragma unroll
            for (int nt = 0; nt < 8; nt++)
                #pragma unroll
                for (int r = 0; r < 4; r++) sf[nt][r] *= 0.125f;
            if (kt == myktmax) {
                #pragma unroll
                for (int nt = 0; nt < 8; nt++) {
                    const int kc = kt * 64 + nt * 8 + 2 * q;
                    if (kc > qrow_g)      sf[nt][0] = -1e30f;
                    if (kc + 1 > qrow_g)  sf[nt][1] = -1e30f;
                    if (kc > qrow_g8)     sf[nt][2] = -1e30f;
                    if (kc + 1 > qrow_g8) sf[nt][3] = -1e30f;
                }
            }

            // online softmax
            float mt0 = -1e30f, mt1 = -1e30f;
            #pragma unroll
            for (int nt = 0; nt < 8; nt++) {
                mt0 = fmaxf(mt0, fmaxf(sf[nt][0], sf[nt][1]));
                mt1 = fmaxf(mt1, fmaxf(sf[nt][2], sf[nt][3]));
            }
            mt0 = fmaxf(mt0, __shfl_xor_sync(0xffffffffu, mt0, 1));
            mt0 = fmaxf(mt0, __shfl_xor_sync(0xffffffffu, mt0, 2));
            mt1 = fmaxf(mt1, __shfl_xor_sync(0xffffffffu, mt1, 1));
            mt1 = fmaxf(mt1, __shfl_xor_sync(0xffffffffu, mt1, 2));

            const float mn0 = fmaxf(m0, mt0);
            const float mn1 = fmaxf(m1, mt1);
            const float corr0 = __expf(m0 - mn0);
            const float corr1 = __expf(m1 - mn1);
            m0 = mn0; m1 = mn1;

            float ls0 = 0.0f, ls1 = 0.0f;
            #pragma unroll
            for (int nt = 0; nt < 8; nt++) {
                sf[nt][0] = __expf(sf[nt][0] - m0);
                sf[nt][1] = __expf(sf[nt][1] - m0);
                sf[nt][2] = __expf(sf[nt][2] - m1);
                sf[nt][3] = __expf(sf[nt][3] - m1);
                ls0 += sf[nt][0] + sf[nt][1];
                ls1 += sf[nt][2] + sf[nt][3];
            }
            ls0 += __shfl_xor_sync(0xffffffffu, ls0, 1);
            ls0 += __shfl_xor_sync(0xffffffffu, ls0, 2);
            ls1 += __shfl_xor_sync(0xffffffffu, ls1, 1);
            ls1 += __shfl_xor_sync(0xffffffffu, ls1, 2);
            l0 = l0 * corr0 + ls0;
            l1 = l1 * corr1 + ls1;
            #pragma unroll
            for (int nt = 0; nt < 8; nt++) {
                of[nt][0] *= corr0; of[nt][1] *= corr0;
                of[nt][2] *= corr1; of[nt][3] *= corr1;
            }
        }

        // write prefetched tile to the other buffer
        if (pre) {
            const uint32_t* kw0 = (const uint32_t*)&k0v;
            const uint32_t* kw1 = (const uint32_t*)&k1v;
            #pragma unroll
            for (int i = 0; i < 4; i++) Ks2[s ^ 1][kdw + i][kr] = kw0[i];
            #pragma unroll
            for (int i = 0; i < 4; i++) Ks2[s ^ 1][kdw + 4 + i][kr] = kw1[i];
            uint32_t vw[8];
            interleave8(va, vb, vw);
            *(uint4*)&Vs2[s ^ 1][vrp][vc]     = *(uint4*)(vw);
            *(uint4*)&Vs2[s ^ 1][vrp][vc + 4] = *(uint4*)(vw + 4);
        }

        if (active) {
            // P (registers) @ V
            #pragma unroll
            for (int j = 0; j < 4; j++) {
                uint32_t pa[4];
                pa[0] = pack_h2(sf[2 * j][0],     sf[2 * j][1]);
                pa[1] = pack_h2(sf[2 * j][2],     sf[2 * j][3]);
                pa[2] = pack_h2(sf[2 * j + 1][0], sf[2 * j + 1][1]);
                pa[3] = pack_h2(sf[2 * j + 1][2], sf[2 * j + 1][3]);
                #pragma unroll
                for (int nt = 0; nt < 8; nt++) {
                    const uint32_t b0 = Vs2[s][8 * j + q][nt * 8 + g];
                    const uint32_t b1 = Vs2[s][8 * j + q + 4][nt * 8 + g];
                    mma_f16(of[nt], pa, b0, b1);
                }
            }
        }

        if (pre) {
            __syncthreads();
            s ^= 1;
        }
    }

    // epilogue: normalize, store half
    const float inv0 = 1.0f / l0;
    const float inv1 = 1.0f / l1;
    __half* o0 = attnh + (size_t)(b * SEQ + qrow_g) * D_MODEL + h * HEAD_DIM;
    __half* o8 = o0 + (size_t)8 * D_MODEL;
    #pragma unroll
    for (int nt = 0; nt < 8; nt++) {
        const int col = nt * 8 + 2 * q;
        *(uint32_t*)(o0 + col) = pack_h2(of[nt][0] * inv0, of[nt][1] * inv0);
        *(uint32_t*)(o8 + col) = pack_h2(of[nt][2] * inv1, of[nt][3] * inv1);
    }
}

extern "C" void kernel_launch(void* const* d_in, const int* in_sizes, int n_in,
                              void* d_out, int out_size)
{
    const float* x     = (const float*)d_in[0];
    const float* qkv_w = (const float*)d_in[1];
    const float* qkv_b = (const float*)d_in[2];
    const float* out_w = (const float*)d_in[3];
    const float* out_b = (const float*)d_in[4];
    float* out = (float*)d_out;

    __half *xh, *w1h, *w2h, *qkvh, *attnh;
    cudaGetSymbolAddress((void**)&xh, g_xh);
    cudaGetSymbolAddress((void**)&w1h, g_w1h);
    cudaGetSymbolAddress((void**)&w2h, g_w2h);
    cudaGetSymbolAddress((void**)&qkvh, g_qkvh);
    cudaGetSymbolAddress((void**)&attnh, g_attnh);

    const int nx = M_ROWS * D_MODEL;
    const int nw1 = D_MODEL * QKV_N;
    const int nw2 = D_MODEL * D_MODEL;
    cvt_f32_f16<<<nx / 2048, 256>>>(x, xh, nx);
    cvt_f32_f16<<<nw1 / 2048, 256>>>(qkv_w, w1h, nw1);
    cvt_f32_f16<<<nw2 / 2048, 256>>>(out_w, w2h, nw2);

    dim3 g1(QKV_N / 128, M_ROWS / 128);
    gemm_f16<true><<<g1, 256>>>(xh, w1h, qkv_b, qkvh, M_ROWS, QKV_N, D_MODEL);

    dim3 g2(SEQ / 128, BATCH * N_HEADS);
    attn_f16<<<g2, 256>>>(qkvh, attnh);

    dim3 g3(D_MODEL / 128, M_ROWS / 128);
    gemm_f16<false><<<g3, 256>>>(attnh, w2h, out_b, out, M_ROWS, D_MODEL, D_MODEL);
}

// round 5
// speedup vs baseline: 9.3983x; 1.3293x over previous
#include <cuda_runtime.h>
#include <cuda_fp16.h>
#include <cstdint>

#define D_MODEL 1024
#define N_HEADS 16
#define HEAD_DIM 64
#define BATCH 4
#define SEQ 2048
#define M_ROWS (BATCH * SEQ)     /* 8192 */
#define QKV_N (3 * D_MODEL)      /* 3072 */

// Scratch (allocation-free)
__device__ __half g_xh[(size_t)M_ROWS * D_MODEL];
__device__ __half g_w1h[(size_t)D_MODEL * QKV_N];
__device__ __half g_w2h[(size_t)D_MODEL * D_MODEL];
__device__ __half g_qkvh[(size_t)M_ROWS * QKV_N];
__device__ __half g_attnh[(size_t)M_ROWS * D_MODEL];

// ---------------------------------------------------------------------------
// helpers
// ---------------------------------------------------------------------------
__device__ __forceinline__ uint32_t pack_h2(float x, float y) {
    __half2 h = __floats2half2_rn(x, y);
    return *reinterpret_cast<uint32_t*>(&h);
}

__device__ __forceinline__ void mma_f16(float* c, const uint32_t* a,
                                        uint32_t b0, uint32_t b1) {
    asm volatile(
        "mma.sync.aligned.m16n8k16.row.col.f32.f16.f16.f32 "
        "{%0,%1,%2,%3}, {%4,%5,%6,%7}, {%8,%9}, {%0,%1,%2,%3};\n"
        : "+f"(c[0]), "+f"(c[1]), "+f"(c[2]), "+f"(c[3])
        : "r"(a[0]), "r"(a[1]), "r"(a[2]), "r"(a[3]), "r"(b0), "r"(b1));
}

__device__ __forceinline__ void ldsm_x4(uint32_t* r, uint32_t a) {
    asm volatile("ldmatrix.sync.aligned.m8n8.x4.shared.b16 {%0,%1,%2,%3}, [%4];"
                 : "=r"(r[0]), "=r"(r[1]), "=r"(r[2]), "=r"(r[3]) : "r"(a));
}
__device__ __forceinline__ void ldsm_x4_t(uint32_t* r, uint32_t a) {
    asm volatile("ldmatrix.sync.aligned.m8n8.x4.trans.shared.b16 {%0,%1,%2,%3}, [%4];"
                 : "=r"(r[0]), "=r"(r[1]), "=r"(r[2]), "=r"(r[3]) : "r"(a));
}

__device__ __forceinline__ void cp_async16(uint32_t dst, const void* src) {
    asm volatile("cp.async.cg.shared.global [%0], [%1], 16;" :: "r"(dst), "l"(src));
}
__device__ __forceinline__ void cp_commit() {
    asm volatile("cp.async.commit_group;");
}
__device__ __forceinline__ void cp_wait0() {
    asm volatile("cp.async.wait_group 0;");
}

__global__ void cvt_f32_f16(const float* __restrict__ in,
                            __half* __restrict__ out, int n) {
    int i = (blockIdx.x * blockDim.x + threadIdx.x) * 8;
    if (i >= n) return;
    float4 v0 = *(const float4*)(in + i);
    float4 v1 = *(const float4*)(in + i + 4);
    uint4 o;
    o.x = pack_h2(v0.x, v0.y); o.y = pack_h2(v0.z, v0.w);
    o.z = pack_h2(v1.x, v1.y); o.w = pack_h2(v1.z, v1.w);
    *(uint4*)(out + i) = o;
}

// ---------------------------------------------------------------------------
// fp16 GEMM with ldmatrix + cp.async. C = A[M,K]@B[K,N] + bias.
// 128x128 tile, BK=64 halves (128B rows), 8 warps (warp 64x32), double buf.
// As: [m][k64] 128B rows, swizzle chunk ^= m&7. ldmatrix.x4 (no trans).
// Bs: [k][n128] 256B rows, swizzle low3(chunk) ^= k&7. ldmatrix.x4.trans.
// ---------------------------------------------------------------------------
template<bool OUT_HALF>
__global__ __launch_bounds__(256, 2) void gemm_f16(
    const __half* __restrict__ A, const __half* __restrict__ B,
    const float* __restrict__ bias, void* __restrict__ Cv,
    int M, int N, int K)
{
    extern __shared__ char smem[];
    const uint32_t sb = (uint32_t)__cvta_generic_to_shared(smem);
    const uint32_t AsB = sb;            // 2 x 16384
    const uint32_t BsB = sb + 32768;    // 2 x 16384

    const int tid  = threadIdx.x;
    const int wid  = tid >> 5;
    const int lane = tid & 31;
    const int wm = (wid >> 2) * 64;
    const int wn = (wid & 3) * 32;
    const int bm = blockIdx.y * 128;
    const int bn = blockIdx.x * 128;

    // ---- staging indices
    const int am = tid >> 1;                 // 0..127
    const int ac0 = (tid & 1) * 4;           // chunk base 0/4
    const int bk0 = tid >> 4;                // 0..15
    const int bc = tid & 15;                 // 0..15

    const __half* Ag = A + (size_t)(bm + am) * K;
    const __half* Bg = B + bn + bc * 8;

    // ---- fragment lane indices
    const int l7 = lane & 7;
    const int mA = l7 + ((lane >> 3) & 1) * 8;          // row in m16 tile
    const int kcA = (lane >> 4) & 1;                    // k chunk offset
    const int kB = ((lane >> 3) & 1) * 8 + l7;          // k within k16 (B frag)
    const int ncB = (lane >> 4) & 1;                    // n chunk offset (B frag)

    float acc[4][4][4];
    #pragma unroll
    for (int i = 0; i < 4; i++)
        #pragma unroll
        for (int j = 0; j < 4; j++)
            #pragma unroll
            for (int r = 0; r < 4; r++) acc[i][j][r] = 0.0f;

    auto stage = [&](int buf, int k0) {
        const uint32_t ad = AsB + buf * 16384 + am * 128;
        #pragma unroll
        for (int i = 0; i < 4; i++) {
            const int c = ac0 + i;
            cp_async16(ad + ((c ^ (am & 7)) << 4), Ag + k0 + c * 8);
        }
        const uint32_t bd = BsB + buf * 16384;
        #pragma unroll
        for (int i = 0; i < 4; i++) {
            const int k = bk0 + 16 * i;
            const int cs = (bc & 8) | ((bc ^ (k & 7)) & 7);
            cp_async16(bd + k * 256 + (cs << 4), Bg + (size_t)(k0 + k) * N);
        }
    };

    stage(0, 0);
    cp_commit();
    cp_wait0();
    __syncthreads();

    const int kIters = K >> 6;
    int s = 0;
    for (int it = 0; it < kIters; ++it) {
        const bool pre = (it + 1 < kIters);
        if (pre) {
            stage(s ^ 1, (it + 1) * 64);
            cp_commit();
        }

        const uint32_t aBuf = AsB + s * 16384;
        const uint32_t bBuf = BsB + s * 16384;
        #pragma unroll
        for (int ks = 0; ks < 4; ks++) {
            uint32_t af[4][4], bf[2][4];
            #pragma unroll
            for (int mt = 0; mt < 4; mt++) {
                const int m = wm + mt * 16 + mA;
                const int ch = (ks * 2 + kcA) ^ (m & 7);
                ldsm_x4(af[mt], aBuf + m * 128 + (ch << 4));
            }
            #pragma unroll
            for (int np = 0; np < 2; np++) {
                const int k = ks * 16 + kB;
                const int chunk = (wn >> 3) + np * 2 + ncB;
                const int cs = (chunk & 8) | ((chunk ^ (k & 7)) & 7);
                ldsm_x4_t(bf[np], bBuf + k * 256 + (cs << 4));
            }
            #pragma unroll
            for (int nt = 0; nt < 4; nt++)
                #pragma unroll
                for (int mt = 0; mt < 4; mt++)
                    mma_f16(acc[mt][nt], af[mt],
                            bf[nt >> 1][(nt & 1) * 2], bf[nt >> 1][(nt & 1) * 2 + 1]);
        }

        if (pre) {
            cp_wait0();
            __syncthreads();
            s ^= 1;
        }
    }

    // Epilogue (fragment rows g/g+8, cols 2q,2q+1)
    const int g = lane >> 2;
    const int q = lane & 3;
    #pragma unroll
    for (int nt = 0; nt < 4; nt++) {
        const int col = bn + wn + nt * 8 + 2 * q;
        const float bia0 = bias[col];
        const float bia1 = bias[col + 1];
        #pragma unroll
        for (int mt = 0; mt < 4; mt++) {
            const int row0 = bm + wm + mt * 16 + g;
            if (OUT_HALF) {
                __half* C = (__half*)Cv;
                *(uint32_t*)&C[(size_t)row0 * N + col] =
                    pack_h2(acc[mt][nt][0] + bia0, acc[mt][nt][1] + bia1);
                *(uint32_t*)&C[(size_t)(row0 + 8) * N + col] =
                    pack_h2(acc[mt][nt][2] + bia0, acc[mt][nt][3] + bia1);
            } else {
                float* C = (float*)Cv;
                float2 v0, v1;
                v0.x = acc[mt][nt][0] + bia0; v0.y = acc[mt][nt][1] + bia1;
                v1.x = acc[mt][nt][2] + bia0; v1.y = acc[mt][nt][3] + bia1;
                *(float2*)&C[(size_t)row0 * N + col] = v0;
                *(float2*)&C[(size_t)(row0 + 8) * N + col] = v1;
            }
        }
    }
}

// ---------------------------------------------------------------------------
// fp16 flash attention: ldmatrix + cp.async, P in registers, double-buffered.
// Block = 128 queries x one (b,h); 8 warps x 16 query rows; KV tiles of 64.
// K/V smem: [key][dim64] 128B rows, swizzle chunk ^= key&7.
// QK^T B-frag: plain ldmatrix.x4 (K rows = n, contiguous = k).
// PV  B-frag: ldmatrix.x4.trans (V rows = k, contiguous = n).
// ---------------------------------------------------------------------------
__global__ __launch_bounds__(256, 2) void attn_f16(
    const __half* __restrict__ qkvh, __half* __restrict__ attnh)
{
    const int qt = blockIdx.x;
    const int bh = blockIdx.y;
    const int b = bh >> 4;
    const int h = bh & 15;

    __shared__ __align__(128) char smem[32768];  // K:2x8K | V:2x8K
    const uint32_t sb = (uint32_t)__cvta_generic_to_shared(smem);
    const uint32_t KsB = sb;
    const uint32_t VsB = sb + 16384;

    const int tid  = threadIdx.x;
    const int wid  = tid >> 5;
    const int lane = tid & 31;
    const int g = lane >> 2;
    const int q = lane & 3;
    const int l7 = lane & 7;

    const int qrow_g  = qt * 128 + wid * 16 + g;
    const int qrow_g8 = qrow_g + 8;

    // staging: row = tid>>2 (0..63), chunks (tid&3), (tid&3)+4
    const int srow = tid >> 2;
    const int sc0 = tid & 3;
    const __half* Kg = qkvh + (size_t)(b * SEQ + srow) * QKV_N + D_MODEL + h * HEAD_DIM;
    const __half* Vg = Kg + D_MODEL;
    const size_t kvStep = (size_t)64 * QKV_N;

    auto stage = [&](int buf, int kt) {
        const size_t off = (size_t)kt * kvStep;
        const uint32_t kd = KsB + buf * 8192 + srow * 128;
        const uint32_t vd = VsB + buf * 8192 + srow * 128;
        #pragma unroll
        for (int i = 0; i < 2; i++) {
            const int c = sc0 + 4 * i;
            const int sw = (c ^ (srow & 7)) << 4;
            cp_async16(kd + sw, Kg + off + c * 8);
            cp_async16(vd + sw, Vg + off + c * 8);
        }
    };

    // Q fragments (persistent, raw fp16; scale applied post-mma)
    uint32_t qf[4][4];
    {
        const __half* qp = qkvh + (size_t)(b * SEQ + qrow_g) * QKV_N + h * HEAD_DIM;
        const __half* qp8 = qp + (size_t)8 * QKV_N;
        #pragma unroll
        for (int j = 0; j < 4; j++) {
            qf[j][0] = *(const uint32_t*)(qp  + 16 * j + 2 * q);
            qf[j][1] = *(const uint32_t*)(qp8 + 16 * j + 2 * q);
            qf[j][2] = *(const uint32_t*)(qp  + 16 * j + 2 * q + 8);
            qf[j][3] = *(const uint32_t*)(qp8 + 16 * j + 2 * q + 8);
        }
    }

    float of[8][4];
    #pragma unroll
    for (int nt = 0; nt < 8; nt++)
        #pragma unroll
        for (int r = 0; r < 4; r++) of[nt][r] = 0.0f;
    float m0 = -1e30f, m1 = -1e30f, l0 = 0.0f, l1 = 0.0f;

    const int ktmax   = 2 * qt + 1;
    const int myktmax = (qt * 128 + wid * 16 + 15) >> 6;

    // fragment lane indices
    const int keyA = ((lane >> 4) & 1) * 8 + l7;   // QK: key row within n16
    const int dcA  = (lane >> 3) & 1;              // QK: dim chunk offset
    const int keyB = ((lane >> 3) & 1) * 8 + l7;   // PV: key row within k16
    const int ncB  = (lane >> 4) & 1;              // PV: dim chunk offset

    stage(0, 0);
    cp_commit();
    cp_wait0();
    __syncthreads();

    int s = 0;
    for (int kt = 0; kt <= ktmax; kt++) {
        const bool active = (kt <= myktmax);
        const bool pre = (kt < ktmax);
        if (pre) {
            stage(s ^ 1, kt + 1);
            cp_commit();
        }

        const uint32_t kBuf = KsB + s * 8192;
        const uint32_t vBuf = VsB + s * 8192;

        float sf[8][4];
        if (active) {
            #pragma unroll
            for (int nt = 0; nt < 8; nt++)
                #pragma unroll
                for (int r = 0; r < 4; r++) sf[nt][r] = 0.0f;
            // S = Q K^T
            #pragma unroll
            for (int kd = 0; kd < 4; kd++) {
                #pragma unroll
                for (int np = 0; np < 4; np++) {
                    const int key = np * 16 + keyA;
                    const int ch = (kd * 2 + dcA) ^ (key & 7);
                    uint32_t bf[4];
                    ldsm_x4(bf, kBuf + key * 128 + (ch << 4));
                    mma_f16(sf[np * 2],     qf[kd], bf[0], bf[1]);
                    mma_f16(sf[np * 2 + 1], qf[kd], bf[2], bf[3]);
                }
            }

            // scale + causal mask
            #pragma unroll
            for (int nt = 0; nt < 8; nt++)
                #pragma unroll
                for (int r = 0; r < 4; r++) sf[nt][r] *= 0.125f;
            if (kt == myktmax) {
                #pragma unroll
                for (int nt = 0; nt < 8; nt++) {
                    const int kc = kt * 64 + nt * 8 + 2 * q;
                    if (kc > qrow_g)      sf[nt][0] = -1e30f;
                    if (kc + 1 > qrow_g)  sf[nt][1] = -1e30f;
                    if (kc > qrow_g8)     sf[nt][2] = -1e30f;
                    if (kc + 1 > qrow_g8) sf[nt][3] = -1e30f;
                }
            }

            // online softmax
            float mt0 = -1e30f, mt1 = -1e30f;
            #pragma unroll
            for (int nt = 0; nt < 8; nt++) {
                mt0 = fmaxf(mt0, fmaxf(sf[nt][0], sf[nt][1]));
                mt1 = fmaxf(mt1, fmaxf(sf[nt][2], sf[nt][3]));
            }
            mt0 = fmaxf(mt0, __shfl_xor_sync(0xffffffffu, mt0, 1));
            mt0 = fmaxf(mt0, __shfl_xor_sync(0xffffffffu, mt0, 2));
            mt1 = fmaxf(mt1, __shfl_xor_sync(0xffffffffu, mt1, 1));
            mt1 = fmaxf(mt1, __shfl_xor_sync(0xffffffffu, mt1, 2));

            const float mn0 = fmaxf(m0, mt0);
            const float mn1 = fmaxf(m1, mt1);
            const float corr0 = __expf(m0 - mn0);
            const float corr1 = __expf(m1 - mn1);
            m0 = mn0; m1 = mn1;

            float ls0 = 0.0f, ls1 = 0.0f;
            #pragma unroll
            for (int nt = 0; nt < 8; nt++) {
                sf[nt][0] = __expf(sf[nt][0] - m0);
                sf[nt][1] = __expf(sf[nt][1] - m0);
                sf[nt][2] = __expf(sf[nt][2] - m1);
                sf[nt][3] = __expf(sf[nt][3] - m1);
                ls0 += sf[nt][0] + sf[nt][1];
                ls1 += sf[nt][2] + sf[nt][3];
            }
            ls0 += __shfl_xor_sync(0xffffffffu, ls0, 1);
            ls0 += __shfl_xor_sync(0xffffffffu, ls0, 2);
            ls1 += __shfl_xor_sync(0xffffffffu, ls1, 1);
            ls1 += __shfl_xor_sync(0xffffffffu, ls1, 2);
            l0 = l0 * corr0 + ls0;
            l1 = l1 * corr1 + ls1;
            #pragma unroll
            for (int nt = 0; nt < 8; nt++) {
                of[nt][0] *= corr0; of[nt][1] *= corr0;
                of[nt][2] *= corr1; of[nt][3] *= corr1;
            }

            // O += P @ V (P packed from sf registers)
            #pragma unroll
            for (int j = 0; j < 4; j++) {
                uint32_t pa[4];
                pa[0] = pack_h2(sf[2 * j][0],     sf[2 * j][1]);
                pa[1] = pack_h2(sf[2 * j][2],     sf[2 * j][3]);
                pa[2] = pack_h2(sf[2 * j + 1][0], sf[2 * j + 1][1]);
                pa[3] = pack_h2(sf[2 * j + 1][2], sf[2 * j + 1][3]);
                #pragma unroll
                for (int np = 0; np < 4; np++) {
                    const int key = j * 16 + keyB;
                    const int ch = (np * 2 + ncB) ^ (key & 7);
                    uint32_t bf[4];
                    ldsm_x4_t(bf, vBuf + key * 128 + (ch << 4));
                    mma_f16(of[np * 2],     pa, bf[0], bf[1]);
                    mma_f16(of[np * 2 + 1], pa, bf[2], bf[3]);
                }
            }
        }

        if (pre) {
            cp_wait0();
            __syncthreads();
            s ^= 1;
        }
    }

    // epilogue
    const float inv0 = 1.0f / l0;
    const float inv1 = 1.0f / l1;
    __half* o0 = attnh + (size_t)(b * SEQ + qrow_g) * D_MODEL + h * HEAD_DIM;
    __half* o8 = o0 + (size_t)8 * D_MODEL;
    #pragma unroll
    for (int nt = 0; nt < 8; nt++) {
        const int col = nt * 8 + 2 * q;
        *(uint32_t*)(o0 + col) = pack_h2(of[nt][0] * inv0, of[nt][1] * inv0);
        *(uint32_t*)(o8 + col) = pack_h2(of[nt][2] * inv1, of[nt][3] * inv1);
    }
}

extern "C" void kernel_launch(void* const* d_in, const int* in_sizes, int n_in,
                              void* d_out, int out_size)
{
    const float* x     = (const float*)d_in[0];
    const float* qkv_w = (const float*)d_in[1];
    const float* qkv_b = (const float*)d_in[2];
    const float* out_w = (const float*)d_in[3];
    const float* out_b = (const float*)d_in[4];
    float* out = (float*)d_out;

    __half *xh, *w1h, *w2h, *qkvh, *attnh;
    cudaGetSymbolAddress((void**)&xh, g_xh);
    cudaGetSymbolAddress((void**)&w1h, g_w1h);
    cudaGetSymbolAddress((void**)&w2h, g_w2h);
    cudaGetSymbolAddress((void**)&qkvh, g_qkvh);
    cudaGetSymbolAddress((void**)&attnh, g_attnh);

    static bool attr_done = false;
    if (!attr_done) {
        cudaFuncSetAttribute(gemm_f16<true>,
                             cudaFuncAttributeMaxDynamicSharedMemorySize, 65536);
        cudaFuncSetAttribute(gemm_f16<false>,
                             cudaFuncAttributeMaxDynamicSharedMemorySize, 65536);
        attr_done = true;
    }

    const int nx = M_ROWS * D_MODEL;
    const int nw1 = D_MODEL * QKV_N;
    const int nw2 = D_MODEL * D_MODEL;
    cvt_f32_f16<<<nx / 2048, 256>>>(x, xh, nx);
    cvt_f32_f16<<<nw1 / 2048, 256>>>(qkv_w, w1h, nw1);
    cvt_f32_f16<<<nw2 / 2048, 256>>>(out_w, w2h, nw2);

    dim3 g1(QKV_N / 128, M_ROWS / 128);
    gemm_f16<true><<<g1, 256, 65536>>>(xh, w1h, qkv_b, qkvh, M_ROWS, QKV_N, D_MODEL);

    dim3 g2(SEQ / 128, BATCH * N_HEADS);
    attn_f16<<<g2, 256>>>(qkvh, attnh);

    dim3 g3(D_MODEL / 128, M_ROWS / 128);
    gemm_f16<false><<<g3, 256, 65536>>>(attnh, w2h, out_b, out, M_ROWS, D_MODEL, D_MODEL);
}

// round 12
// speedup vs baseline: 9.4628x; 1.0069x over previous
#include <cuda_runtime.h>
#include <cuda_fp16.h>
#include <cstdint>

#define D_MODEL 1024
#define N_HEADS 16
#define HEAD_DIM 64
#define BATCH 4
#define SEQ 2048
#define M_ROWS (BATCH * SEQ)     /* 8192 */
#define QKV_N (3 * D_MODEL)      /* 3072 */

// Scratch (allocation-free)
__device__ __half g_xh[(size_t)M_ROWS * D_MODEL];
__device__ __half g_w1h[(size_t)D_MODEL * QKV_N];
__device__ __half g_w2h[(size_t)D_MODEL * D_MODEL];
__device__ __half g_qkvh[(size_t)M_ROWS * QKV_N];
__device__ __half g_attnh[(size_t)M_ROWS * D_MODEL];

// ---------------------------------------------------------------------------
// helpers
// ---------------------------------------------------------------------------
__device__ __forceinline__ uint32_t pack_h2(float x, float y) {
    __half2 h = __floats2half2_rn(x, y);
    return *reinterpret_cast<uint32_t*>(&h);
}

__device__ __forceinline__ void mma_f16(float* c, const uint32_t* a,
                                        uint32_t b0, uint32_t b1) {
    asm volatile(
        "mma.sync.aligned.m16n8k16.row.col.f32.f16.f16.f32 "
        "{%0,%1,%2,%3}, {%4,%5,%6,%7}, {%8,%9}, {%0,%1,%2,%3};\n"
        : "+f"(c[0]), "+f"(c[1]), "+f"(c[2]), "+f"(c[3])
        : "r"(a[0]), "r"(a[1]), "r"(a[2]), "r"(a[3]), "r"(b0), "r"(b1));
}

__device__ __forceinline__ void ldsm_x4(uint32_t* r, uint32_t a) {
    asm volatile("ldmatrix.sync.aligned.m8n8.x4.shared.b16 {%0,%1,%2,%3}, [%4];"
                 : "=r"(r[0]), "=r"(r[1]), "=r"(r[2]), "=r"(r[3]) : "r"(a));
}
__device__ __forceinline__ void ldsm_x4_t(uint32_t* r, uint32_t a) {
    asm volatile("ldmatrix.sync.aligned.m8n8.x4.trans.shared.b16 {%0,%1,%2,%3}, [%4];"
                 : "=r"(r[0]), "=r"(r[1]), "=r"(r[2]), "=r"(r[3]) : "r"(a));
}

__device__ __forceinline__ void cp_async16(uint32_t dst, const void* src) {
    asm volatile("cp.async.cg.shared.global [%0], [%1], 16;" :: "r"(dst), "l"(src));
}
__device__ __forceinline__ void cp_commit() {
    asm volatile("cp.async.commit_group;");
}
__device__ __forceinline__ void cp_wait0() {
    asm volatile("cp.async.wait_group 0;");
}
__device__ __forceinline__ void cp_wait1() {
    asm volatile("cp.async.wait_group 1;");
}

__global__ void cvt_f32_f16(const float* __restrict__ in,
                            __half* __restrict__ out, int n) {
    int i = (blockIdx.x * blockDim.x + threadIdx.x) * 8;
    if (i >= n) return;
    float4 v0 = *(const float4*)(in + i);
    float4 v1 = *(const float4*)(in + i + 4);
    uint4 o;
    o.x = pack_h2(v0.x, v0.y); o.y = pack_h2(v0.z, v0.w);
    o.z = pack_h2(v1.x, v1.y); o.w = pack_h2(v1.z, v1.w);
    *(uint4*)(out + i) = o;
}

// ---------------------------------------------------------------------------
// fp16 GEMM, ldmatrix + cp.async, 3-stage pipeline. C = A[M,K]@B[K,N] + bias.
// 128x128 tile, BK=64 halves (128B rows), 8 warps (warp 64x32).
// As: [m][k64] 128B rows, swizzle chunk ^= m&7. ldmatrix.x4 (no trans).
// Bs: [k][n128] 256B rows, swizzle low3(chunk) ^= k&7. ldmatrix.x4.trans.
// ---------------------------------------------------------------------------
template<bool OUT_HALF>
__global__ __launch_bounds__(256, 2) void gemm_f16(
    const __half* __restrict__ A, const __half* __restrict__ B,
    const float* __restrict__ bias, void* __restrict__ Cv,
    int M, int N, int K)
{
    extern __shared__ char smem[];
    const uint32_t sb = (uint32_t)__cvta_generic_to_shared(smem);
    const uint32_t AsB = sb;            // 3 x 16384
    const uint32_t BsB = sb + 49152;    // 3 x 16384

    const int tid  = threadIdx.x;
    const int wid  = tid >> 5;
    const int lane = tid & 31;
    const int wm = (wid >> 2) * 64;
    const int wn = (wid & 3) * 32;
    const int bm = blockIdx.y * 128;
    const int bn = blockIdx.x * 128;

    // ---- staging indices
    const int am = tid >> 1;                 // 0..127
    const int ac0 = (tid & 1) * 4;           // chunk base 0/4
    const int bk0 = tid >> 4;                // 0..15
    const int bc = tid & 15;                 // 0..15

    const __half* Ag = A + (size_t)(bm + am) * K;
    const __half* Bg = B + bn + bc * 8;

    // ---- fragment lane indices
    const int l7 = lane & 7;
    const int mA = l7 + ((lane >> 3) & 1) * 8;          // row in m16 tile
    const int kcA = (lane >> 4) & 1;                    // k chunk offset
    const int kB = ((lane >> 3) & 1) * 8 + l7;          // k within k16 (B frag)
    const int ncB = (lane >> 4) & 1;                    // n chunk offset (B frag)

    float acc[4][4][4];
    #pragma unroll
    for (int i = 0; i < 4; i++)
        #pragma unroll
        for (int j = 0; j < 4; j++)
            #pragma unroll
            for (int r = 0; r < 4; r++) acc[i][j][r] = 0.0f;

    auto stage = [&](int buf, int k0) {
        const uint32_t ad = AsB + buf * 16384 + am * 128;
        #pragma unroll
        for (int i = 0; i < 4; i++) {
            const int c = ac0 + i;
            cp_async16(ad + ((c ^ (am & 7)) << 4), Ag + k0 + c * 8);
        }
        const uint32_t bd = BsB + buf * 16384;
        #pragma unroll
        for (int i = 0; i < 4; i++) {
            const int k = bk0 + 16 * i;
            const int cs = (bc & 8) | ((bc ^ (k & 7)) & 7);
            cp_async16(bd + k * 256 + (cs << 4), Bg + (size_t)(k0 + k) * N);
        }
    };

    const int kIters = K >> 6;

    // prologue: 2 stages in flight
    stage(0, 0);
    cp_commit();
    stage(1, 64);
    cp_commit();

    for (int it = 0; it < kIters; ++it) {
        if (it == kIters - 1) cp_wait0(); else cp_wait1();
        __syncthreads();

        if (it + 2 < kIters) {
            stage((it + 2) % 3, (it + 2) * 64);
            cp_commit();
        }

        const int s = it % 3;
        const uint32_t aBuf = AsB + s * 16384;
        const uint32_t bBuf = BsB + s * 16384;
        #pragma unroll
        for (int ks = 0; ks < 4; ks++) {
            uint32_t af[4][4], bf[2][4];
            #pragma unroll
            for (int mt = 0; mt < 4; mt++) {
                const int m = wm + mt * 16 + mA;
                const int ch = (ks * 2 + kcA) ^ (m & 7);
                ldsm_x4(af[mt], aBuf + m * 128 + (ch << 4));
            }
            #pragma unroll
            for (int np = 0; np < 2; np++) {
                const int k = ks * 16 + kB;
                const int chunk = (wn >> 3) + np * 2 + ncB;
                const int cs = (chunk & 8) | ((chunk ^ (k & 7)) & 7);
                ldsm_x4_t(bf[np], bBuf + k * 256 + (cs << 4));
            }
            #pragma unroll
            for (int nt = 0; nt < 4; nt++)
                #pragma unroll
                for (int mt = 0; mt < 4; mt++)
                    mma_f16(acc[mt][nt], af[mt],
                            bf[nt >> 1][(nt & 1) * 2], bf[nt >> 1][(nt & 1) * 2 + 1]);
        }
    }

    // Epilogue (fragment rows g/g+8, cols 2q,2q+1)
    const int g = lane >> 2;
    const int q = lane & 3;
    #pragma unroll
    for (int nt = 0; nt < 4; nt++) {
        const int col = bn + wn + nt * 8 + 2 * q;
        const float bia0 = bias[col];
        const float bia1 = bias[col + 1];
        #pragma unroll
        for (int mt = 0; mt < 4; mt++) {
            const int row0 = bm + wm + mt * 16 + g;
            if (OUT_HALF) {
                __half* C = (__half*)Cv;
                *(uint32_t*)&C[(size_t)row0 * N + col] =
                    pack_h2(acc[mt][nt][0] + bia0, acc[mt][nt][1] + bia1);
                *(uint32_t*)&C[(size_t)(row0 + 8) * N + col] =
                    pack_h2(acc[mt][nt][2] + bia0, acc[mt][nt][3] + bia1);
            } else {
                float* C = (float*)Cv;
                float2 v0, v1;
                v0.x = acc[mt][nt][0] + bia0; v0.y = acc[mt][nt][1] + bia1;
                v1.x = acc[mt][nt][2] + bia0; v1.y = acc[mt][nt][3] + bia1;
                *(float2*)&C[(size_t)row0 * N + col] = v0;
                *(float2*)&C[(size_t)(row0 + 8) * N + col] = v1;
            }
        }
    }
}

// ---------------------------------------------------------------------------
// fp16 flash attention: ldmatrix + cp.async, P in registers, 3-stage pipeline,
// exp2-domain softmax. Block = 128 queries x one (b,h); 8 warps x 16 q rows;
// KV tiles of 64. K/V smem: [key][dim64] 128B rows, swizzle chunk ^= key&7.
// ---------------------------------------------------------------------------
__global__ __launch_bounds__(256, 2) void attn_f16(
    const __half* __restrict__ qkvh, __half* __restrict__ attnh)
{
    const int qt = blockIdx.x;
    const int bh = blockIdx.y;
    const int b = bh >> 4;
    const int h = bh & 15;

    __shared__ __align__(128) char smem[49152];  // K:3x8K | V:3x8K
    const uint32_t sb = (uint32_t)__cvta_generic_to_shared(smem);
    const uint32_t KsB = sb;
    const uint32_t VsB = sb + 24576;

    const int tid  = threadIdx.x;
    const int wid  = tid >> 5;
    const int lane = tid & 31;
    const int g = lane >> 2;
    const int q = lane & 3;
    const int l7 = lane & 7;

    const int qrow_g  = qt * 128 + wid * 16 + g;
    const int qrow_g8 = qrow_g + 8;

    // scale * log2(e): softmax done in exp2 domain
    const float SC = 0.125f * 1.4426950408889634f;

    const int srow = tid >> 2;
    const int sc0 = tid & 3;
    const __half* Kg = qkvh + (size_t)(b * SEQ + srow) * QKV_N + D_MODEL + h * HEAD_DIM;
    const __half* Vg = Kg + D_MODEL;
    const size_t kvStep = (size_t)64 * QKV_N;

    auto stage = [&](int buf, int kt) {
        const size_t off = (size_t)kt * kvStep;
        const uint32_t kd = KsB + buf * 8192 + srow * 128;
        const uint32_t vd = VsB + buf * 8192 + srow * 128;
        #pragma unroll
        for (int i = 0; i < 2; i++) {
            const int c = sc0 + 4 * i;
            const int sw = (c ^ (srow & 7)) << 4;
            cp_async16(kd + sw, Kg + off + c * 8);
            cp_async16(vd + sw, Vg + off + c * 8);
        }
    };

    // Q fragments (persistent, raw fp16; SC applied post-mma)
    uint32_t qf[4][4];
    {
        const __half* qp = qkvh + (size_t)(b * SEQ + qrow_g) * QKV_N + h * HEAD_DIM;
        const __half* qp8 = qp + (size_t)8 * QKV_N;
        #pragma unroll
        for (int j = 0; j < 4; j++) {
            qf[j][0] = *(const uint32_t*)(qp  + 16 * j + 2 * q);
            qf[j][1] = *(const uint32_t*)(qp8 + 16 * j + 2 * q);
            qf[j][2] = *(const uint32_t*)(qp  + 16 * j + 2 * q + 8);
            qf[j][3] = *(const uint32_t*)(qp8 + 16 * j + 2 * q + 8);
        }
    }

    float of[8][4];
    #pragma unroll
    for (int nt = 0; nt < 8; nt++)
        #pragma unroll
        for (int r = 0; r < 4; r++) of[nt][r] = 0.0f;
    float m0 = -1e30f, m1 = -1e30f, l0 = 0.0f, l1 = 0.0f;

    const int ktmax   = 2 * qt + 1;                       // >= 1 always
    const int myktmax = (qt * 128 + wid * 16 + 15) >> 6;

    const int keyA = ((lane >> 4) & 1) * 8 + l7;
    const int dcA  = (lane >> 3) & 1;
    const int keyB = ((lane >> 3) & 1) * 8 + l7;
    const int ncB  = (lane >> 4) & 1;

    // prologue: 2 stages in flight
    stage(0, 0);
    cp_commit();
    stage(1, 1);
    cp_commit();

    for (int kt = 0; kt <= ktmax; kt++) {
        if (kt == ktmax) cp_wait0(); else cp_wait1();
        __syncthreads();

        if (kt + 2 <= ktmax) {
            stage((kt + 2) % 3, kt + 2);
            cp_commit();
        }

        const bool active = (kt <= myktmax);
        const int s = kt % 3;
        const uint32_t kBuf = KsB + s * 8192;
        const uint32_t vBuf = VsB + s * 8192;

        if (active) {
            float sf[8][4];
            #pragma unroll
            for (int nt = 0; nt < 8; nt++)
                #pragma unroll
                for (int r = 0; r < 4; r++) sf[nt][r] = 0.0f;
            // S = Q K^T
            #pragma unroll
            for (int kd = 0; kd < 4; kd++) {
                #pragma unroll
                for (int np = 0; np < 4; np++) {
                    const int key = np * 16 + keyA;
                    const int ch = (kd * 2 + dcA) ^ (key & 7);
                    uint32_t bf[4];
                    ldsm_x4(bf, kBuf + key * 128 + (ch << 4));
                    mma_f16(sf[np * 2],     qf[kd], bf[0], bf[1]);
                    mma_f16(sf[np * 2 + 1], qf[kd], bf[2], bf[3]);
                }
            }

            // scale into exp2 domain + causal mask
            #pragma unroll
            for (int nt = 0; nt < 8; nt++)
                #pragma unroll
                for (int r = 0; r < 4; r++) sf[nt][r] *= SC;
            if (kt == myktmax) {
                #pragma unroll
                for (int nt = 0; nt < 8; nt++) {
                    const int kc = kt * 64 + nt * 8 + 2 * q;
                    if (kc > qrow_g)      sf[nt][0] = -1e30f;
                    if (kc + 1 > qrow_g)  sf[nt][1] = -1e30f;
                    if (kc > qrow_g8)     sf[nt][2] = -1e30f;
                    if (kc + 1 > qrow_g8) sf[nt][3] = -1e30f;
                }
            }

            // online softmax (exp2 domain)
            float mt0 = -1e30f, mt1 = -1e30f;
            #pragma unroll
            for (int nt = 0; nt < 8; nt++) {
                mt0 = fmaxf(mt0, fmaxf(sf[nt][0], sf[nt][1]));
                mt1 = fmaxf(mt1, fmaxf(sf[nt][2], sf[nt][3]));
            }
            mt0 = fmaxf(mt0, __shfl_xor_sync(0xffffffffu, mt0, 1));
            mt0 = fmaxf(mt0, __shfl_xor_sync(0xffffffffu, mt0, 2));
            mt1 = fmaxf(mt1, __shfl_xor_sync(0xffffffffu, mt1, 1));
            mt1 = fmaxf(mt1, __shfl_xor_sync(0xffffffffu, mt1, 2));

            const float mn0 = fmaxf(m0, mt0);
            const float mn1 = fmaxf(m1, mt1);
            const float corr0 = exp2f(m0 - mn0);
            const float corr1 = exp2f(m1 - mn1);
            m0 = mn0; m1 = mn1;

            float ls0 = 0.0f, ls1 = 0.0f;
            #pragma unroll
            for (int nt = 0; nt < 8; nt++) {
                sf[nt][0] = exp2f(sf[nt][0] - m0);
                sf[nt][1] = exp2f(sf[nt][1] - m0);
                sf[nt][2] = exp2f(sf[nt][2] - m1);
                sf[nt][3] = exp2f(sf[nt][3] - m1);
                ls0 += sf[nt][0] + sf[nt][1];
                ls1 += sf[nt][2] + sf[nt][3];
            }
            ls0 += __shfl_xor_sync(0xffffffffu, ls0, 1);
            ls0 += __shfl_xor_sync(0xffffffffu, ls0, 2);
            ls1 += __shfl_xor_sync(0xffffffffu, ls1, 1);
            ls1 += __shfl_xor_sync(0xffffffffu, ls1, 2);
            l0 = l0 * corr0 + ls0;
            l1 = l1 * corr1 + ls1;
            #pragma unroll
            for (int nt = 0; nt < 8; nt++) {
                of[nt][0] *= corr0; of[nt][1] *= corr0;
                of[nt][2] *= corr1; of[nt][3] *= corr1;
            }

            // O += P @ V (P packed from registers)
            #pragma unroll
            for (int j = 0; j < 4; j++) {
                uint32_t pa[4];
                pa[0] = pack_h2(sf[2 * j][0],     sf[2 * j][1]);
                pa[1] = pack_h2(sf[2 * j][2],     sf[2 * j][3]);
                pa[2] = pack_h2(sf[2 * j + 1][0], sf[2 * j + 1][1]);
                pa[3] = pack_h2(sf[2 * j + 1][2], sf[2 * j + 1][3]);
                #pragma unroll
                for (int np = 0; np < 4; np++) {
                    const int key = j * 16 + keyB;
                    const int ch = (np * 2 + ncB) ^ (key & 7);
                    uint32_t bf[4];
                    ldsm_x4_t(bf, vBuf + key * 128 + (ch << 4));
                    mma_f16(of[np * 2],     pa, bf[0], bf[1]);
                    mma_f16(of[np * 2 + 1], pa, bf[2], bf[3]);
                }
            }
        }
    }

    // epilogue
    const float inv0 = 1.0f / l0;
    const float inv1 = 1.0f / l1;
    __half* o0 = attnh + (size_t)(b * SEQ + qrow_g) * D_MODEL + h * HEAD_DIM;
    __half* o8 = o0 + (size_t)8 * D_MODEL;
    #pragma unroll
    for (int nt = 0; nt < 8; nt++) {
        const int col = nt * 8 + 2 * q;
        *(uint32_t*)(o0 + col) = pack_h2(of[nt][0] * inv0, of[nt][1] * inv0);
        *(uint32_t*)(o8 + col) = pack_h2(of[nt][2] * inv1, of[nt][3] * inv1);
    }
}

extern "C" void kernel_launch(void* const* d_in, const int* in_sizes, int n_in,
                              void* d_out, int out_size)
{
    const float* x     = (const float*)d_in[0];
    const float* qkv_w = (const float*)d_in[1];
    const float* qkv_b = (const float*)d_in[2];
    const float* out_w = (const float*)d_in[3];
    const float* out_b = (const float*)d_in[4];
    float* out = (float*)d_out;

    __half *xh, *w1h, *w2h, *qkvh, *attnh;
    cudaGetSymbolAddress((void**)&xh, g_xh);
    cudaGetSymbolAddress((void**)&w1h, g_w1h);
    cudaGetSymbolAddress((void**)&w2h, g_w2h);
    cudaGetSymbolAddress((void**)&qkvh, g_qkvh);
    cudaGetSymbolAddress((void**)&attnh, g_attnh);

    static bool attr_done = false;
    if (!attr_done) {
        cudaFuncSetAttribute(gemm_f16<true>,
                             cudaFuncAttributeMaxDynamicSharedMemorySize, 98304);
        cudaFuncSetAttribute(gemm_f16<false>,
                             cudaFuncAttributeMaxDynamicSharedMemorySize, 98304);
        attr_done = true;
    }

    const int nx = M_ROWS * D_MODEL;
    const int nw1 = D_MODEL * QKV_N;
    const int nw2 = D_MODEL * D_MODEL;
    cvt_f32_f16<<<nx / 2048, 256>>>(x, xh, nx);
    cvt_f32_f16<<<nw1 / 2048, 256>>>(qkv_w, w1h, nw1);
    cvt_f32_f16<<<nw2 / 2048, 256>>>(out_w, w2h, nw2);

    // 1) QKV projection: [8192,1024] @ [1024,3072] + b -> fp16
    dim3 g1(QKV_N / 128, M_ROWS / 128);
    gemm_f16<true><<<g1, 256, 98304>>>(xh, w1h, qkv_b, qkvh, M_ROWS, QKV_N, D_MODEL);

    // 2) Causal flash attention
    dim3 g2(SEQ / 128, BATCH * N_HEADS);
    attn_f16<<<g2, 256>>>(qkvh, attnh);

    // 3) Output projection: [8192,1024] @ [1024,1024] + b -> fp32
    dim3 g3(D_MODEL / 128, M_ROWS / 128);
    gemm_f16<false><<<g3, 256, 98304>>>(attnh, w2h, out_b, out, M_ROWS, D_MODEL, D_MODEL);
}

// round 14
// speedup vs baseline: 9.7555x; 1.0309x over previous
#include <cuda_runtime.h>
#include <cuda_fp16.h>
#include <cstdint>

#define D_MODEL 1024
#define N_HEADS 16
#define HEAD_DIM 64
#define BATCH 4
#define SEQ 2048
#define M_ROWS (BATCH * SEQ)     /* 8192 */
#define QKV_N (3 * D_MODEL)      /* 3072 */

// Scratch (allocation-free)
__device__ __half g_xh[(size_t)M_ROWS * D_MODEL];
__device__ __half g_w1h[(size_t)D_MODEL * QKV_N];
__device__ __half g_w2h[(size_t)D_MODEL * D_MODEL];
__device__ __half g_qkvh[(size_t)M_ROWS * QKV_N];
__device__ __half g_attnh[(size_t)M_ROWS * D_MODEL];

// ---------------------------------------------------------------------------
// helpers
// ---------------------------------------------------------------------------
__device__ __forceinline__ uint32_t pack_h2(float x, float y) {
    __half2 h = __floats2half2_rn(x, y);
    return *reinterpret_cast<uint32_t*>(&h);
}

__device__ __forceinline__ float fast_ex2(float x) {
    float r;
    asm("ex2.approx.ftz.f32 %0, %1;" : "=f"(r) : "f"(x));
    return r;
}

__device__ __forceinline__ void mma_f16(float* c, const uint32_t* a,
                                        uint32_t b0, uint32_t b1) {
    asm volatile(
        "mma.sync.aligned.m16n8k16.row.col.f32.f16.f16.f32 "
        "{%0,%1,%2,%3}, {%4,%5,%6,%7}, {%8,%9}, {%0,%1,%2,%3};\n"
        : "+f"(c[0]), "+f"(c[1]), "+f"(c[2]), "+f"(c[3])
        : "r"(a[0]), "r"(a[1]), "r"(a[2]), "r"(a[3]), "r"(b0), "r"(b1));
}

__device__ __forceinline__ void ldsm_x4(uint32_t* r, uint32_t a) {
    asm volatile("ldmatrix.sync.aligned.m8n8.x4.shared.b16 {%0,%1,%2,%3}, [%4];"
                 : "=r"(r[0]), "=r"(r[1]), "=r"(r[2]), "=r"(r[3]) : "r"(a));
}
__device__ __forceinline__ void ldsm_x4_t(uint32_t* r, uint32_t a) {
    asm volatile("ldmatrix.sync.aligned.m8n8.x4.trans.shared.b16 {%0,%1,%2,%3}, [%4];"
                 : "=r"(r[0]), "=r"(r[1]), "=r"(r[2]), "=r"(r[3]) : "r"(a));
}

__device__ __forceinline__ void cp_async16(uint32_t dst, const void* src) {
    asm volatile("cp.async.cg.shared.global [%0], [%1], 16;" :: "r"(dst), "l"(src));
}
__device__ __forceinline__ void cp_commit() {
    asm volatile("cp.async.commit_group;");
}
__device__ __forceinline__ void cp_wait0() {
    asm volatile("cp.async.wait_group 0;");
}
__device__ __forceinline__ void cp_wait1() {
    asm volatile("cp.async.wait_group 1;");
}

// one launch converts x, qkv_w, out_w
__global__ void cvt_all_f16(const float* __restrict__ a, __half* __restrict__ oa, int na,
                            const float* __restrict__ b, __half* __restrict__ ob, int nb,
                            const float* __restrict__ c, __half* __restrict__ oc, int nc)
{
    int i = (blockIdx.x * blockDim.x + threadIdx.x) * 8;
    const float* in;
    __half* out;
    if (i < na) { in = a + i; out = oa + i; }
    else if (i < na + nb) { in = b + (i - na); out = ob + (i - na); }
    else if (i < na + nb + nc) { in = c + (i - na - nb); out = oc + (i - na - nb); }
    else return;
    float4 v0 = *(const float4*)(in);
    float4 v1 = *(const float4*)(in + 4);
    uint4 o;
    o.x = pack_h2(v0.x, v0.y); o.y = pack_h2(v0.z, v0.w);
    o.z = pack_h2(v1.x, v1.y); o.w = pack_h2(v1.z, v1.w);
    *(uint4*)(out) = o;
}

// ---------------------------------------------------------------------------
// fp16 GEMM, ldmatrix + cp.async, 3-stage smem pipeline + register fragment
// double-buffering. C = A[M,K]@B[K,N] + bias. 128x128 tile, BK=64, 8 warps
// (warp 64x32). NO occupancy cap: ptxas gets register headroom to pipeline.
// ---------------------------------------------------------------------------
template<bool OUT_HALF>
__global__ __launch_bounds__(256) void gemm_f16(
    const __half* __restrict__ A, const __half* __restrict__ B,
    const float* __restrict__ bias, void* __restrict__ Cv,
    int M, int N, int K)
{
    extern __shared__ char smem[];
    const uint32_t sb = (uint32_t)__cvta_generic_to_shared(smem);
    const uint32_t AsB = sb;            // 3 x 16384
    const uint32_t BsB = sb + 49152;    // 3 x 16384

    const int tid  = threadIdx.x;
    const int wid  = tid >> 5;
    const int lane = tid & 31;
    const int wm = (wid >> 2) * 64;
    const int wn = (wid & 3) * 32;
    const int bm = blockIdx.y * 128;
    const int bn = blockIdx.x * 128;

    // ---- staging indices
    const int am = tid >> 1;                 // 0..127
    const int ac0 = (tid & 1) * 4;           // chunk base 0/4
    const int bk0 = tid >> 4;                // 0..15
    const int bc = tid & 15;                 // 0..15

    const __half* Ag = A + (size_t)(bm + am) * K;
    const __half* Bg = B + bn + bc * 8;

    // ---- fragment lane indices
    const int l7 = lane & 7;
    const int mA = l7 + ((lane >> 3) & 1) * 8;          // row in m16 tile
    const int kcA = (lane >> 4) & 1;                    // k chunk offset
    const int kB = ((lane >> 3) & 1) * 8 + l7;          // k within k16 (B frag)
    const int ncB = (lane >> 4) & 1;                    // n chunk offset (B frag)

    float acc[4][4][4];
    #pragma unroll
    for (int i = 0; i < 4; i++)
        #pragma unroll
        for (int j = 0; j < 4; j++)
            #pragma unroll
            for (int r = 0; r < 4; r++) acc[i][j][r] = 0.0f;

    auto stage = [&](int buf, int k0) {
        const uint32_t ad = AsB + buf * 16384 + am * 128;
        #pragma unroll
        for (int i = 0; i < 4; i++) {
            const int c = ac0 + i;
            cp_async16(ad + ((c ^ (am & 7)) << 4), Ag + k0 + c * 8);
        }
        const uint32_t bd = BsB + buf * 16384;
        #pragma unroll
        for (int i = 0; i < 4; i++) {
            const int k = bk0 + 16 * i;
            const int cs = (bc & 8) | ((bc ^ (k & 7)) & 7);
            cp_async16(bd + k * 256 + (cs << 4), Bg + (size_t)(k0 + k) * N);
        }
    };

    // register fragment double buffer
    uint32_t af[2][4][4], bf[2][2][4];
    auto load_frags = [&](uint32_t aBuf, uint32_t bBuf, int ks, int pb) {
        #pragma unroll
        for (int mt = 0; mt < 4; mt++) {
            const int m = wm + mt * 16 + mA;
            const int ch = (ks * 2 + kcA) ^ (m & 7);
            ldsm_x4(af[pb][mt], aBuf + m * 128 + (ch << 4));
        }
        #pragma unroll
        for (int np = 0; np < 2; np++) {
            const int k = ks * 16 + kB;
            const int chunk = (wn >> 3) + np * 2 + ncB;
            const int cs = (chunk & 8) | ((chunk ^ (k & 7)) & 7);
            ldsm_x4_t(bf[pb][np], bBuf + k * 256 + (cs << 4));
        }
    };

    const int kIters = K >> 6;

    // prologue: 2 smem stages in flight
    stage(0, 0);
    cp_commit();
    stage(1, 64);
    cp_commit();

    for (int it = 0; it < kIters; ++it) {
        if (it == kIters - 1) cp_wait0(); else cp_wait1();
        __syncthreads();

        if (it + 2 < kIters) {
            stage((it + 2) % 3, (it + 2) * 64);
            cp_commit();
        }

        const int s = it % 3;
        const uint32_t aBuf = AsB + s * 16384;
        const uint32_t bBuf = BsB + s * 16384;

        load_frags(aBuf, bBuf, 0, 0);
        #pragma unroll
        for (int ks = 0; ks < 4; ks++) {
            const int cur = ks & 1;
            if (ks < 3) load_frags(aBuf, bBuf, ks + 1, cur ^ 1);
            #pragma unroll
            for (int nt = 0; nt < 4; nt++)
                #pragma unroll
                for (int mt = 0; mt < 4; mt++)
                    mma_f16(acc[mt][nt], af[cur][mt],
                            bf[cur][nt >> 1][(nt & 1) * 2],
                            bf[cur][nt >> 1][(nt & 1) * 2 + 1]);
        }
    }

    // Epilogue (fragment rows g/g+8, cols 2q,2q+1)
    const int g = lane >> 2;
    const int q = lane & 3;
    #pragma unroll
    for (int nt = 0; nt < 4; nt++) {
        const int col = bn + wn + nt * 8 + 2 * q;
        const float bia0 = bias[col];
        const float bia1 = bias[col + 1];
        #pragma unroll
        for (int mt = 0; mt < 4; mt++) {
            const int row0 = bm + wm + mt * 16 + g;
            if (OUT_HALF) {
                __half* C = (__half*)Cv;
                *(uint32_t*)&C[(size_t)row0 * N + col] =
                    pack_h2(acc[mt][nt][0] + bia0, acc[mt][nt][1] + bia1);
                *(uint32_t*)&C[(size_t)(row0 + 8) * N + col] =
                    pack_h2(acc[mt][nt][2] + bia0, acc[mt][nt][3] + bia1);
            } else {
                float* C = (float*)Cv;
                float2 v0, v1;
                v0.x = acc[mt][nt][0] + bia0; v0.y = acc[mt][nt][1] + bia1;
                v1.x = acc[mt][nt][2] + bia0; v1.y = acc[mt][nt][3] + bia1;
                *(float2*)&C[(size_t)row0 * N + col] = v0;
                *(float2*)&C[(size_t)(row0 + 8) * N + col] = v1;
            }
        }
    }
}

// ---------------------------------------------------------------------------
// fp16 flash attention: ldmatrix + cp.async, P in registers, 3-stage pipeline,
// exp2-domain softmax (MUFU.EX2). Blocks launched big-first (qt reversed) for
// wave packing. Block = 128 queries x one (b,h); 8 warps x 16 q rows.
// ---------------------------------------------------------------------------
__global__ __launch_bounds__(256, 2) void attn_f16(
    const __half* __restrict__ qkvh, __half* __restrict__ attnh)
{
    const int qt = (SEQ / 128 - 1) - blockIdx.x;   // reversed: big tiles first
    const int bh = blockIdx.y;
    const int b = bh >> 4;
    const int h = bh & 15;

    __shared__ __align__(128) char smem[49152];  // K:3x8K | V:3x8K
    const uint32_t sb = (uint32_t)__cvta_generic_to_shared(smem);
    const uint32_t KsB = sb;
    const uint32_t VsB = sb + 24576;

    const int tid  = threadIdx.x;
    const int wid  = tid >> 5;
    const int lane = tid & 31;
    const int g = lane >> 2;
    const int q = lane & 3;
    const int l7 = lane & 7;

    const int qrow_g  = qt * 128 + wid * 16 + g;
    const int qrow_g8 = qrow_g + 8;

    // scale * log2(e): softmax done in exp2 domain
    const float SC = 0.125f * 1.4426950408889634f;

    const int srow = tid >> 2;
    const int sc0 = tid & 3;
    const __half* Kg = qkvh + (size_t)(b * SEQ + srow) * QKV_N + D_MODEL + h * HEAD_DIM;
    const __half* Vg = Kg + D_MODEL;
    const size_t kvStep = (size_t)64 * QKV_N;

    auto stage = [&](int buf, int kt) {
        const size_t off = (size_t)kt * kvStep;
        const uint32_t kd = KsB + buf * 8192 + srow * 128;
        const uint32_t vd = VsB + buf * 8192 + srow * 128;
        #pragma unroll
        for (int i = 0; i < 2; i++) {
            const int c = sc0 + 4 * i;
            const int sw = (c ^ (srow & 7)) << 4;
            cp_async16(kd + sw, Kg + off + c * 8);
            cp_async16(vd + sw, Vg + off + c * 8);
        }
    };

    // Q fragments (persistent, raw fp16; SC applied post-mma)
    uint32_t qf[4][4];
    {
        const __half* qp = qkvh + (size_t)(b * SEQ + qrow_g) * QKV_N + h * HEAD_DIM;
        const __half* qp8 = qp + (size_t)8 * QKV_N;
        #pragma unroll
        for (int j = 0; j < 4; j++) {
            qf[j][0] = *(const uint32_t*)(qp  + 16 * j + 2 * q);
            qf[j][1] = *(const uint32_t*)(qp8 + 16 * j + 2 * q);
            qf[j][2] = *(const uint32_t*)(qp  + 16 * j + 2 * q + 8);
            qf[j][3] = *(const uint32_t*)(qp8 + 16 * j + 2 * q + 8);
        }
    }

    float of[8][4];
    #pragma unroll
    for (int nt = 0; nt < 8; nt++)
        #pragma unroll
        for (int r = 0; r < 4; r++) of[nt][r] = 0.0f;
    float m0 = -1e30f, m1 = -1e30f, l0 = 0.0f, l1 = 0.0f;

    const int ktmax   = 2 * qt + 1;                       // >= 1 always
    const int myktmax = (qt * 128 + wid * 16 + 15) >> 6;

    const int keyA = ((lane >> 4) & 1) * 8 + l7;
    const int dcA  = (lane >> 3) & 1;
    const int keyB = ((lane >> 3) & 1) * 8 + l7;
    const int ncB  = (lane >> 4) & 1;

    // prologue: 2 stages in flight
    stage(0, 0);
    cp_commit();
    stage(1, 1);
    cp_commit();

    for (int kt = 0; kt <= ktmax; kt++) {
        if (kt == ktmax) cp_wait0(); else cp_wait1();
        __syncthreads();

        if (kt + 2 <= ktmax) {
            stage((kt + 2) % 3, kt + 2);
            cp_commit();
        }

        const bool active = (kt <= myktmax);
        const int s = kt % 3;
        const uint32_t kBuf = KsB + s * 8192;
        const uint32_t vBuf = VsB + s * 8192;

        if (active) {
            float sf[8][4];
            #pragma unroll
            for (int nt = 0; nt < 8; nt++)
                #pragma unroll
                for (int r = 0; r < 4; r++) sf[nt][r] = 0.0f;
            // S = Q K^T
            #pragma unroll
            for (int kd = 0; kd < 4; kd++) {
                #pragma unroll
                for (int np = 0; np < 4; np++) {
                    const int key = np * 16 + keyA;
                    const int ch = (kd * 2 + dcA) ^ (key & 7);
                    uint32_t bf[4];
                    ldsm_x4(bf, kBuf + key * 128 + (ch << 4));
                    mma_f16(sf[np * 2],     qf[kd], bf[0], bf[1]);
                    mma_f16(sf[np * 2 + 1], qf[kd], bf[2], bf[3]);
                }
            }

            // scale into exp2 domain + causal mask
            #pragma unroll
            for (int nt = 0; nt < 8; nt++)
                #pragma unroll
                for (int r = 0; r < 4; r++) sf[nt][r] *= SC;
            if (kt == myktmax) {
                #pragma unroll
                for (int nt = 0; nt < 8; nt++) {
                    const int kc = kt * 64 + nt * 8 + 2 * q;
                    if (kc > qrow_g)      sf[nt][0] = -1e30f;
                    if (kc + 1 > qrow_g)  sf[nt][1] = -1e30f;
                    if (kc > qrow_g8)     sf[nt][2] = -1e30f;
                    if (kc + 1 > qrow_g8) sf[nt][3] = -1e30f;
                }
            }

            // online softmax (exp2 domain)
            float mt0 = -1e30f, mt1 = -1e30f;
            #pragma unroll
            for (int nt = 0; nt < 8; nt++) {
                mt0 = fmaxf(mt0, fmaxf(sf[nt][0], sf[nt][1]));
                mt1 = fmaxf(mt1, fmaxf(sf[nt][2], sf[nt][3]));
            }
            mt0 = fmaxf(mt0, __shfl_xor_sync(0xffffffffu, mt0, 1));
            mt0 = fmaxf(mt0, __shfl_xor_sync(0xffffffffu, mt0, 2));
            mt1 = fmaxf(mt1, __shfl_xor_sync(0xffffffffu, mt1, 1));
            mt1 = fmaxf(mt1, __shfl_xor_sync(0xffffffffu, mt1, 2));

            const float mn0 = fmaxf(m0, mt0);
            const float mn1 = fmaxf(m1, mt1);
            const float corr0 = fast_ex2(m0 - mn0);
            const float corr1 = fast_ex2(m1 - mn1);
            m0 = mn0; m1 = mn1;

            float ls0 = 0.0f, ls1 = 0.0f;
            #pragma unroll
            for (int nt = 0; nt < 8; nt++) {
                sf[nt][0] = fast_ex2(sf[nt][0] - m0);
                sf[nt][1] = fast_ex2(sf[nt][1] - m0);
                sf[nt][2] = fast_ex2(sf[nt][2] - m1);
                sf[nt][3] = fast_ex2(sf[nt][3] - m1);
                ls0 += sf[nt][0] + sf[nt][1];
                ls1 += sf[nt][2] + sf[nt][3];
            }
            ls0 += __shfl_xor_sync(0xffffffffu, ls0, 1);
            ls0 += __shfl_xor_sync(0xffffffffu, ls0, 2);
            ls1 += __shfl_xor_sync(0xffffffffu, ls1, 1);
            ls1 += __shfl_xor_sync(0xffffffffu, ls1, 2);
            l0 = l0 * corr0 + ls0;
            l1 = l1 * corr1 + ls1;
            #pragma unroll
            for (int nt = 0; nt < 8; nt++) {
                of[nt][0] *= corr0; of[nt][1] *= corr0;
                of[nt][2] *= corr1; of[nt][3] *= corr1;
            }

            // O += P @ V (P packed from registers)
            #pragma unroll
            for (int j = 0; j < 4; j++) {
                uint32_t pa[4];
                pa[0] = pack_h2(sf[2 * j][0],     sf[2 * j][1]);
                pa[1] = pack_h2(sf[2 * j][2],     sf[2 * j][3]);
                pa[2] = pack_h2(sf[2 * j + 1][0], sf[2 * j + 1][1]);
                pa[3] = pack_h2(sf[2 * j + 1][2], sf[2 * j + 1][3]);
                #pragma unroll
                for (int np = 0; np < 4; np++) {
                    const int key = j * 16 + keyB;
                    const int ch = (np * 2 + ncB) ^ (key & 7);
                    uint32_t bf[4];
                    ldsm_x4_t(bf, vBuf + key * 128 + (ch << 4));
                    mma_f16(of[np * 2],     pa, bf[0], bf[1]);
                    mma_f16(of[np * 2 + 1], pa, bf[2], bf[3]);
                }
            }
        }
    }

    // epilogue
    const float inv0 = 1.0f / l0;
    const float inv1 = 1.0f / l1;
    __half* o0 = attnh + (size_t)(b * SEQ + qrow_g) * D_MODEL + h * HEAD_DIM;
    __half* o8 = o0 + (size_t)8 * D_MODEL;
    #pragma unroll
    for (int nt = 0; nt < 8; nt++) {
        const int col = nt * 8 + 2 * q;
        *(uint32_t*)(o0 + col) = pack_h2(of[nt][0] * inv0, of[nt][1] * inv0);
        *(uint32_t*)(o8 + col) = pack_h2(of[nt][2] * inv1, of[nt][3] * inv1);
    }
}

extern "C" void kernel_launch(void* const* d_in, const int* in_sizes, int n_in,
                              void* d_out, int out_size)
{
    const float* x     = (const float*)d_in[0];
    const float* qkv_w = (const float*)d_in[1];
    const float* qkv_b = (const float*)d_in[2];
    const float* out_w = (const float*)d_in[3];
    const float* out_b = (const float*)d_in[4];
    float* out = (float*)d_out;

    __half *xh, *w1h, *w2h, *qkvh, *attnh;
    cudaGetSymbolAddress((void**)&xh, g_xh);
    cudaGetSymbolAddress((void**)&w1h, g_w1h);
    cudaGetSymbolAddress((void**)&w2h, g_w2h);
    cudaGetSymbolAddress((void**)&qkvh, g_qkvh);
    cudaGetSymbolAddress((void**)&attnh, g_attnh);

    static bool attr_done = false;
    if (!attr_done) {
        cudaFuncSetAttribute(gemm_f16<true>,
                             cudaFuncAttributeMaxDynamicSharedMemorySize, 98304);
        cudaFuncSetAttribute(gemm_f16<false>,
                             cudaFuncAttributeMaxDynamicSharedMemorySize, 98304);
        attr_done = true;
    }

    const int nx = M_ROWS * D_MODEL;
    const int nw1 = D_MODEL * QKV_N;
    const int nw2 = D_MODEL * D_MODEL;
    const int ntot = nx + nw1 + nw2;
    cvt_all_f16<<<ntot / 2048, 256>>>(x, xh, nx, qkv_w, w1h, nw1, out_w, w2h, nw2);

    // 1) QKV projection: [8192,1024] @ [1024,3072] + b -> fp16
    dim3 g1(QKV_N / 128, M_ROWS / 128);
    gemm_f16<true><<<g1, 256, 98304>>>(xh, w1h, qkv_b, qkvh, M_ROWS, QKV_N, D_MODEL);

    // 2) Causal flash attention (big tiles first)
    dim3 g2(SEQ / 128, BATCH * N_HEADS);
    attn_f16<<<g2, 256>>>(qkvh, attnh);

    // 3) Output projection: [8192,1024] @ [1024,1024] + b -> fp32
    dim3 g3(D_MODEL / 128, M_ROWS / 128);
    gemm_f16<false><<<g3, 256, 98304>>>(attnh, w2h, out_b, out, M_ROWS, D_MODEL, D_MODEL);
}